// round 2
// baseline (speedup 1.0000x reference)
#include <cuda_runtime.h>
#include <math.h>

#define TT 64
#define BSZ 128
#define HD 512
#define NLA 15
#define BH (BSZ*HD)
#define HH (HD*HD)

__device__ float g_h[2][NLA][BH];
__device__ float g_c[2][NLA][BH];
__device__ float g_hg[2][BH];
__device__ float g_ic[NLA][BH];
__device__ float g_cc[NLA][BH];
__device__ float g_t1[5][BH];
__device__ float g_t2[5][BH];
__device__ float g_cat[BSZ*5*HD];
__device__ float g_slp[4][BH];

__device__ __forceinline__ float sigf(float x){ return 1.0f/(1.0f+expf(-x)); }

__global__ void zero_kernel(float* h0, float* c0, float* hg0){
    int n = NLA*BH;
    for (int i = blockIdx.x*blockDim.x+threadIdx.x; i < n; i += gridDim.x*blockDim.x){
        h0[i]=0.f; c0[i]=0.f; if (i<BH) hg0[i]=0.f;
    }
}

// Multi-gate dual-A NT GEMM + fused gate epilogue.
// P_g[m,n] = sum_k A1[m,k]W1[g*512+n,k] + A2[m,k]W2[g*512+n,k] + bias[g*512+n]
// LSTM: c=sig(f)*aux+sig(i)*tanh(g); out1=sig(o)*tanh(c); out2=c
// cell: out1=sig(p0)*aux; out2=sig(p1)*tanh(p2)+out1
template <int NG, bool LSTM>
__global__ __launch_bounds__(128) void mg_gemm(
    const float* __restrict__ A1b, long a1zs,
    const float* __restrict__ A2b, long a2zs,
    const float* __restrict__ W1b, const float* __restrict__ W2b, long wzs,
    const float* __restrict__ biasb, long bzs,
    const float* __restrict__ auxb, long xzs,
    float* __restrict__ out1b, float* __restrict__ out2b, long ozs)
{
    const int z = blockIdx.z;
    const float* A1 = A1b + (long)z*a1zs;
    const float* A2 = A2b + (long)z*a2zs;
    const float* W1 = W1b + (long)z*wzs;
    const float* W2 = W2b + (long)z*wzs;
    const float* bias = biasb + (long)z*bzs;
    const float* aux = auxb + (long)z*xzs;
    float* out1 = out1b + (long)z*ozs;
    float* out2 = out2b + (long)z*ozs;
    const int m0 = blockIdx.y*32, n0 = blockIdx.x*64;

    __shared__ float As1[16][32], As2[16][32];
    __shared__ float Ws1[NG][16][64], Ws2[NG][16][64];

    const int tid = threadIdx.x, tx = tid&15, ty = tid>>4;
    float acc[NG][4][4];
#pragma unroll
    for (int g=0;g<NG;g++)
#pragma unroll
        for (int i=0;i<4;i++)
#pragma unroll
            for (int j=0;j<4;j++) acc[g][i][j]=0.f;

    const int alm = tid>>2, alk = (tid&3)<<2;
    const int wlm = tid>>1, wlk = (tid&1)<<3;

    for (int k0=0;k0<512;k0+=16){
        float4 v;
        v = *(const float4*)(A1 + (long)(m0+alm)*512 + k0+alk);
        As1[alk][alm]=v.x; As1[alk+1][alm]=v.y; As1[alk+2][alm]=v.z; As1[alk+3][alm]=v.w;
        v = *(const float4*)(A2 + (long)(m0+alm)*512 + k0+alk);
        As2[alk][alm]=v.x; As2[alk+1][alm]=v.y; As2[alk+2][alm]=v.z; As2[alk+3][alm]=v.w;
#pragma unroll
        for (int g=0;g<NG;g++){
            const float* wr = W1 + (long)(g*512+n0+wlm)*512 + k0+wlk;
            float4 u0=*(const float4*)wr, u1=*(const float4*)(wr+4);
            Ws1[g][wlk][wlm]=u0.x; Ws1[g][wlk+1][wlm]=u0.y; Ws1[g][wlk+2][wlm]=u0.z; Ws1[g][wlk+3][wlm]=u0.w;
            Ws1[g][wlk+4][wlm]=u1.x; Ws1[g][wlk+5][wlm]=u1.y; Ws1[g][wlk+6][wlm]=u1.z; Ws1[g][wlk+7][wlm]=u1.w;
            wr = W2 + (long)(g*512+n0+wlm)*512 + k0+wlk;
            u0=*(const float4*)wr; u1=*(const float4*)(wr+4);
            Ws2[g][wlk][wlm]=u0.x; Ws2[g][wlk+1][wlm]=u0.y; Ws2[g][wlk+2][wlm]=u0.z; Ws2[g][wlk+3][wlm]=u0.w;
            Ws2[g][wlk+4][wlm]=u1.x; Ws2[g][wlk+5][wlm]=u1.y; Ws2[g][wlk+6][wlm]=u1.z; Ws2[g][wlk+7][wlm]=u1.w;
        }
        __syncthreads();
#pragma unroll
        for (int kk=0;kk<16;kk++){
            float a1[4],a2[4];
#pragma unroll
            for (int i=0;i<4;i++){ a1[i]=As1[kk][ty*4+i]; a2[i]=As2[kk][ty*4+i]; }
#pragma unroll
            for (int g=0;g<NG;g++){
                float w1[4],w2[4];
#pragma unroll
                for (int j=0;j<4;j++){ w1[j]=Ws1[g][kk][tx*4+j]; w2[j]=Ws2[g][kk][tx*4+j]; }
#pragma unroll
                for (int i=0;i<4;i++)
#pragma unroll
                    for (int j=0;j<4;j++) acc[g][i][j] += a1[i]*w1[j] + a2[i]*w2[j];
            }
        }
        __syncthreads();
    }
#pragma unroll
    for (int i=0;i<4;i++){
        int m = m0+ty*4+i;
#pragma unroll
        for (int j=0;j<4;j++){
            int n = n0+tx*4+j;
            float p[NG];
#pragma unroll
            for (int g=0;g<NG;g++) p[g] = acc[g][i][j] + bias[g*512+n];
            float av = aux[(long)m*512+n];
            long o = (long)m*512+n;
            if (LSTM){
                float cn = sigf(p[1])*av + sigf(p[0])*tanhf(p[2]);
                out1[o] = sigf(p[3])*tanhf(cn);
                out2[o] = cn;
            } else {
                float icv = sigf(p[0])*av;
                out1[o] = icv;
                out2[o] = sigf(p[1])*tanhf(p[2]) + icv;
            }
        }
    }
}

// t1/t2: axis-summed dual NN GEMM vs Wilc. z = level l.
__global__ __launch_bounds__(128) void t12_kernel(
    const float* __restrict__ icb, const float* __restrict__ ccb,
    const float* __restrict__ Wilc, const float* __restrict__ bilc,
    float* __restrict__ t1s, float* __restrict__ t2s)
{
    const int l = blockIdx.z, m0 = blockIdx.y*32, n0 = blockIdx.x*64;
    __shared__ float As1[16][32], As2[16][32], Ws[16][64];
    const int tid = threadIdx.x, tx = tid&15, ty = tid>>4;
    float a1c[4][4], a2c[4][4];
#pragma unroll
    for (int i=0;i<4;i++)
#pragma unroll
        for (int j=0;j<4;j++){ a1c[i][j]=0.f; a2c[i][j]=0.f; }
    const int alm = tid>>2, alk = (tid&3)<<2;
    const int wn = (tid&7)<<3, wk = tid>>3;

    for (int a=0;a<3;a++){
        const float* A1 = icb + (long)(l*3+a)*BH;
        const float* A2 = ccb + (long)(l*3+a)*BH;
        const float* W  = Wilc + (long)(l*3+a)*HH;
        for (int k0=0;k0<512;k0+=16){
            float4 v;
            v = *(const float4*)(A1 + (long)(m0+alm)*512 + k0+alk);
            As1[alk][alm]=v.x; As1[alk+1][alm]=v.y; As1[alk+2][alm]=v.z; As1[alk+3][alm]=v.w;
            v = *(const float4*)(A2 + (long)(m0+alm)*512 + k0+alk);
            As2[alk][alm]=v.x; As2[alk+1][alm]=v.y; As2[alk+2][alm]=v.z; As2[alk+3][alm]=v.w;
            *(float4*)&Ws[wk][wn]   = *(const float4*)(W + (long)(k0+wk)*512 + n0+wn);
            *(float4*)&Ws[wk][wn+4] = *(const float4*)(W + (long)(k0+wk)*512 + n0+wn+4);
            __syncthreads();
#pragma unroll
            for (int kk=0;kk<16;kk++){
                float a1[4],a2[4],w[4];
#pragma unroll
                for (int i=0;i<4;i++){ a1[i]=As1[kk][ty*4+i]; a2[i]=As2[kk][ty*4+i]; }
#pragma unroll
                for (int j=0;j<4;j++) w[j]=Ws[kk][tx*4+j];
#pragma unroll
                for (int i=0;i<4;i++)
#pragma unroll
                    for (int j=0;j<4;j++){ a1c[i][j]+=a1[i]*w[j]; a2c[i][j]+=a2[i]*w[j]; }
            }
            __syncthreads();
        }
    }
#pragma unroll
    for (int i=0;i<4;i++){
        int m = m0+ty*4+i;
#pragma unroll
        for (int j=0;j<4;j++){
            int n = n0+tx*4+j;
            float bs = bilc[(long)(l*3)*512+n] + bilc[(long)(l*3+1)*512+n] + bilc[(long)(l*3+2)*512+n];
            t1s[(long)l*BH + (long)m*512 + n] = a1c[i][j] + bs;
            t2s[(long)l*BH + (long)m*512 + n] = a2c[i][j] + bs;
        }
    }
}

// comb: sigmoid(t2)*softmax(t1) -> cat[b, l*512+z]
__global__ void comb_kernel(const float* __restrict__ t1s, const float* __restrict__ t2s,
                            float* __restrict__ cat)
{
    int b = blockIdx.x, l = blockIdx.y, tid = threadIdx.x;
    const float* r1 = t1s + (long)l*BH + (long)b*512;
    const float* r2 = t2s + (long)l*BH + (long)b*512;
    float v[4];
#pragma unroll
    for (int i=0;i<4;i++) v[i] = r1[tid + i*128];
    float mx = fmaxf(fmaxf(v[0],v[1]), fmaxf(v[2],v[3]));
    __shared__ float red[128];
    red[tid] = mx; __syncthreads();
    for (int st=64; st>0; st>>=1){ if (tid<st) red[tid]=fmaxf(red[tid],red[tid+st]); __syncthreads(); }
    mx = red[0]; __syncthreads();
    float e[4], sm=0.f;
#pragma unroll
    for (int i=0;i<4;i++){ e[i]=expf(v[i]-mx); sm+=e[i]; }
    red[tid]=sm; __syncthreads();
    for (int st=64; st>0; st>>=1){ if (tid<st) red[tid]+=red[tid+st]; __syncthreads(); }
    float inv = 1.f/red[0];
#pragma unroll
    for (int i=0;i<4;i++){
        int zz = tid + i*128;
        cat[(long)b*2560 + l*512 + zz] = sigf(r2[zz]) * e[i] * inv;
    }
}

// single_li split-K partials: part[kz][b,h]
__global__ __launch_bounds__(128) void sl_partial(
    const float* __restrict__ cat, const float* __restrict__ Wsl, float* __restrict__ part)
{
    const int kz = blockIdx.z, m0 = blockIdx.y*32, n0 = blockIdx.x*64;
    __shared__ float As[16][32], Ws[16][64];
    const int tid = threadIdx.x, tx = tid&15, ty = tid>>4;
    float acc[4][4];
#pragma unroll
    for (int i=0;i<4;i++)
#pragma unroll
        for (int j=0;j<4;j++) acc[i][j]=0.f;
    const int alm = tid>>2, alk = (tid&3)<<2;
    const int wlm = tid>>1, wlk = (tid&1)<<3;
    const int kb = kz*640;
    for (int k0=kb;k0<kb+640;k0+=16){
        float4 v = *(const float4*)(cat + (long)(m0+alm)*2560 + k0+alk);
        As[alk][alm]=v.x; As[alk+1][alm]=v.y; As[alk+2][alm]=v.z; As[alk+3][alm]=v.w;
        const float* wr = Wsl + (long)(n0+wlm)*2560 + k0+wlk;
        float4 u0=*(const float4*)wr, u1=*(const float4*)(wr+4);
        Ws[wlk][wlm]=u0.x; Ws[wlk+1][wlm]=u0.y; Ws[wlk+2][wlm]=u0.z; Ws[wlk+3][wlm]=u0.w;
        Ws[wlk+4][wlm]=u1.x; Ws[wlk+5][wlm]=u1.y; Ws[wlk+6][wlm]=u1.z; Ws[wlk+7][wlm]=u1.w;
        __syncthreads();
#pragma unroll
        for (int kk=0;kk<16;kk++){
            float a[4],w[4];
#pragma unroll
            for (int i=0;i<4;i++) a[i]=As[kk][ty*4+i];
#pragma unroll
            for (int j=0;j<4;j++) w[j]=Ws[kk][tx*4+j];
#pragma unroll
            for (int i=0;i<4;i++)
#pragma unroll
                for (int j=0;j<4;j++) acc[i][j]+=a[i]*w[j];
        }
        __syncthreads();
    }
#pragma unroll
    for (int i=0;i<4;i++){
        int m = m0+ty*4+i;
#pragma unroll
        for (int j=0;j<4;j++)
            part[(long)kz*BH + (long)m*512 + n0+tx*4+j] = acc[i][j];
    }
}

// combine partials + bias -> h_g; fused per-step linear -> y[b]
__global__ void y_kernel(const float* __restrict__ part, const float* __restrict__ bsl,
                         float* __restrict__ hg, const float* __restrict__ wlin_t,
                         const float* __restrict__ blin_t, float* __restrict__ outp)
{
    int b = blockIdx.x, tid = threadIdx.x;
    float s = 0.f;
    for (int j=tid; j<512; j+=128){
        long idx = (long)b*512 + j;
        float h = bsl[j] + part[idx] + part[BH+idx] + part[2L*BH+idx] + part[3L*BH+idx];
        hg[idx] = h;
        s += h * wlin_t[j];
    }
    __shared__ float red[128];
    red[tid]=s; __syncthreads();
    for (int st=64; st>0; st>>=1){ if (tid<st) red[tid]+=red[tid+st]; __syncthreads(); }
    if (tid==0) outp[b] = red[0] + blin_t[0];
}

extern "C" void kernel_launch(void* const* d_in, const int* in_sizes, int n_in,
                              void* d_out, int out_size)
{
    const float* x     = (const float*)d_in[0];
    const float* Wx    = (const float*)d_in[1];
    const float* Wh    = (const float*)d_in[2];
    const float* bl    = (const float*)d_in[3];
    const float* Wg_h  = (const float*)d_in[4];
    const float* Wg_p  = (const float*)d_in[5];
    const float* bg    = (const float*)d_in[6];
    const float* Wilc  = (const float*)d_in[7];
    const float* bilc  = (const float*)d_in[8];
    const float* Wsl   = (const float*)d_in[9];
    const float* bsl   = (const float*)d_in[10];
    const float* Wlin  = (const float*)d_in[11];
    const float* blin  = (const float*)d_in[12];
    float* out = (float*)d_out;

    float *h, *c, *hg, *ic, *cc, *t1, *t2, *cat, *slp;
    cudaGetSymbolAddress((void**)&h,  g_h);
    cudaGetSymbolAddress((void**)&c,  g_c);
    cudaGetSymbolAddress((void**)&hg, g_hg);
    cudaGetSymbolAddress((void**)&ic, g_ic);
    cudaGetSymbolAddress((void**)&cc, g_cc);
    cudaGetSymbolAddress((void**)&t1, g_t1);
    cudaGetSymbolAddress((void**)&t2, g_t2);
    cudaGetSymbolAddress((void**)&cat, g_cat);
    cudaGetSymbolAddress((void**)&slp, g_slp);

    zero_kernel<<<256,256>>>(h, c, hg);

    for (int t=0; t<TT; t++){
        int p = t & 1, q = p ^ 1;
        const float* hp = h + (long)p*NLA*BH;
        float*       hq = h + (long)q*NLA*BH;
        const float* cp = c + (long)p*NLA*BH;
        float*       cq = c + (long)q*NLA*BH;
        const float* hgp = hg + (long)p*BH;
        float*       hgq = hg + (long)q*BH;

        for (int l=0; l<5; l++){
            const float* A1 = (l==0) ? (x + (long)t*BH) : (hq + (long)(l-1)*3*BH);
            long a1zs = (l==0) ? 0 : BH;
            mg_gemm<4,true><<<dim3(8,4,3),128>>>(
                A1, a1zs, hp + (long)l*3*BH, BH,
                Wx + (long)l*4*HH, Wh + (long)l*4*HH, 5L*4*HH,
                bl + (long)l*4*HD, 5L*4*HD,
                cp + (long)l*3*BH, BH,
                hq + (long)l*3*BH, cq + (long)l*3*BH, BH);
        }
        mg_gemm<3,false><<<dim3(8,4,15),128>>>(
            hgp, 0, hq, BH,
            Wg_h, Wg_p, 3L*HH,
            bg, 3L*HD,
            cq, BH,
            ic, cc, BH);
        t12_kernel<<<dim3(8,4,5),128>>>(ic, cc, Wilc, bilc, t1, t2);
        comb_kernel<<<dim3(128,5),128>>>(t1, t2, cat);
        sl_partial<<<dim3(8,4,4),128>>>(cat, Wsl, slp);
        y_kernel<<<128,128>>>(slp, bsl, hgq, Wlin + (long)t*HD, blin + t, out + (long)t*BSZ);
    }
}

// round 3
// speedup vs baseline: 1.9644x; 1.9644x over previous
#include <cuda_runtime.h>
#include <math.h>

#define TT 64
#define BSZ 128
#define HD 512
#define NLA 15
#define BH (BSZ*HD)
#define HH (HD*HD)

__device__ float g_h[2][NLA][BH];
__device__ float g_c[2][NLA][BH];
__device__ float g_hg[2][BH];
__device__ float g_ic[NLA][BH];
__device__ float g_cc[NLA][BH];
__device__ float g_t1[5][BH];
__device__ float g_t2[5][BH];
__device__ float g_cat[BSZ*5*HD];
__device__ float g_slp[4][BH];

__device__ __forceinline__ float sigf(float x){ return 1.0f/(1.0f+expf(-x)); }

__global__ void zero_kernel(float* h0, float* c0, float* hg0){
    int n = NLA*BH;
    for (int i = blockIdx.x*blockDim.x+threadIdx.x; i < n; i += gridDim.x*blockDim.x){
        h0[i]=0.f; c0[i]=0.f; if (i<BH) hg0[i]=0.f;
    }
}

// Multi-gate dual-A NT GEMM + fused gate epilogue.
// BM=16 rows, BN=32 cols per gate, BK=16, 128 threads, microtile 2x2 per gate.
// P_g[m,n] = sum_k A1[m,k]W1[g*512+n,k] + A2[m,k]W2[g*512+n,k] + bias[g*512+n]
// LSTM: c=sig(f)*aux+sig(i)*tanh(g); out1=sig(o)*tanh(c); out2=c
// cell: out1=sig(p0)*aux; out2=sig(p1)*tanh(p2)+out1
template <int NG, bool LSTM>
__global__ __launch_bounds__(128) void mg16(
    const float* __restrict__ A1b, long a1zs,
    const float* __restrict__ A2b, long a2zs,
    const float* __restrict__ W1b, const float* __restrict__ W2b, long wzs,
    const float* __restrict__ biasb, long bzs,
    const float* __restrict__ auxb, long xzs,
    float* __restrict__ out1b, float* __restrict__ out2b, long ozs)
{
    const int z = blockIdx.z;
    const float* A1 = A1b + (long)z*a1zs;
    const float* A2 = A2b + (long)z*a2zs;
    const float* W1 = W1b + (long)z*wzs;
    const float* W2 = W2b + (long)z*wzs;
    const float* bias = biasb + (long)z*bzs;
    const float* aux = auxb + (long)z*xzs;
    float* out1 = out1b + (long)z*ozs;
    float* out2 = out2b + (long)z*ozs;
    const int m0 = blockIdx.y*16, n0 = blockIdx.x*32;

    __shared__ float As1[16][16], As2[16][16];
    __shared__ float Ws1[NG][16][32], Ws2[NG][16][32];

    const int tid = threadIdx.x, tx = tid&15, ty = tid>>4;
    float acc[NG][2][2];
#pragma unroll
    for (int g=0;g<NG;g++)
#pragma unroll
        for (int i=0;i<2;i++)
#pragma unroll
            for (int j=0;j<2;j++) acc[g][i][j]=0.f;

    const int arow = (tid&63)>>2, akc = (tid&3)<<2;   // 16 rows x 4 k-chunks
    const int wgrp = tid>>5, wn = tid&31;             // 4 groups x 32 lanes

    for (int k0=0;k0<512;k0+=16){
        // A tiles: threads 0-63 -> As1, 64-127 -> As2
        {
            const float* Ab = (tid < 64) ? A1 : A2;
            float* As = (tid < 64) ? &As1[0][0] : &As2[0][0];
            float4 v = *(const float4*)(Ab + (long)(m0+arow)*512 + k0+akc);
            As[(akc  )*16 + arow] = v.x;
            As[(akc+1)*16 + arow] = v.y;
            As[(akc+2)*16 + arow] = v.z;
            As[(akc+3)*16 + arow] = v.w;
        }
        // W tiles: group g loads gate g (both mats), full 16-k row of its n
#pragma unroll
        for (int g = wgrp; g < NG; g += 4){
            const float* wr = W1 + (long)(g*512+n0+wn)*512 + k0;
            float4 u0=*(const float4*)wr, u1=*(const float4*)(wr+4),
                   u2=*(const float4*)(wr+8), u3=*(const float4*)(wr+12);
            Ws1[g][0][wn]=u0.x;  Ws1[g][1][wn]=u0.y;  Ws1[g][2][wn]=u0.z;  Ws1[g][3][wn]=u0.w;
            Ws1[g][4][wn]=u1.x;  Ws1[g][5][wn]=u1.y;  Ws1[g][6][wn]=u1.z;  Ws1[g][7][wn]=u1.w;
            Ws1[g][8][wn]=u2.x;  Ws1[g][9][wn]=u2.y;  Ws1[g][10][wn]=u2.z; Ws1[g][11][wn]=u2.w;
            Ws1[g][12][wn]=u3.x; Ws1[g][13][wn]=u3.y; Ws1[g][14][wn]=u3.z; Ws1[g][15][wn]=u3.w;
            wr = W2 + (long)(g*512+n0+wn)*512 + k0;
            u0=*(const float4*)wr; u1=*(const float4*)(wr+4);
            u2=*(const float4*)(wr+8); u3=*(const float4*)(wr+12);
            Ws2[g][0][wn]=u0.x;  Ws2[g][1][wn]=u0.y;  Ws2[g][2][wn]=u0.z;  Ws2[g][3][wn]=u0.w;
            Ws2[g][4][wn]=u1.x;  Ws2[g][5][wn]=u1.y;  Ws2[g][6][wn]=u1.z;  Ws2[g][7][wn]=u1.w;
            Ws2[g][8][wn]=u2.x;  Ws2[g][9][wn]=u2.y;  Ws2[g][10][wn]=u2.z; Ws2[g][11][wn]=u2.w;
            Ws2[g][12][wn]=u3.x; Ws2[g][13][wn]=u3.y; Ws2[g][14][wn]=u3.z; Ws2[g][15][wn]=u3.w;
        }
        __syncthreads();
#pragma unroll
        for (int kk=0;kk<16;kk++){
            float2 a1 = *(const float2*)&As1[kk][ty*2];
            float2 a2 = *(const float2*)&As2[kk][ty*2];
#pragma unroll
            for (int g=0;g<NG;g++){
                float2 w1 = *(const float2*)&Ws1[g][kk][tx*2];
                float2 w2 = *(const float2*)&Ws2[g][kk][tx*2];
                acc[g][0][0] += a1.x*w1.x + a2.x*w2.x;
                acc[g][0][1] += a1.x*w1.y + a2.x*w2.y;
                acc[g][1][0] += a1.y*w1.x + a2.y*w2.x;
                acc[g][1][1] += a1.y*w1.y + a2.y*w2.y;
            }
        }
        __syncthreads();
    }
#pragma unroll
    for (int i=0;i<2;i++){
        int m = m0+ty*2+i;
#pragma unroll
        for (int j=0;j<2;j++){
            int n = n0+tx*2+j;
            float p[NG];
#pragma unroll
            for (int g=0;g<NG;g++) p[g] = acc[g][i][j] + bias[g*512+n];
            float av = aux[(long)m*512+n];
            long o = (long)m*512+n;
            if (LSTM){
                float cn = sigf(p[1])*av + sigf(p[0])*tanhf(p[2]);
                out1[o] = sigf(p[3])*tanhf(cn);
                out2[o] = cn;
            } else {
                float icv = sigf(p[0])*av;
                out1[o] = icv;
                out2[o] = sigf(p[1])*tanhf(p[2]) + icv;
            }
        }
    }
}

// t1/t2: axis-summed dual-ACC NN GEMM vs Wilc. BM=16, BN=64, grid(8,8,5).
__global__ __launch_bounds__(128) void t12_kernel(
    const float* __restrict__ icb, const float* __restrict__ ccb,
    const float* __restrict__ Wilc, const float* __restrict__ bilc,
    float* __restrict__ t1s, float* __restrict__ t2s)
{
    const int l = blockIdx.z, m0 = blockIdx.y*16, n0 = blockIdx.x*64;
    __shared__ float As1[16][16], As2[16][16], Ws[16][64];
    const int tid = threadIdx.x, tx = tid&15, ty = tid>>4;
    float a1c[2][4], a2c[2][4];
#pragma unroll
    for (int i=0;i<2;i++)
#pragma unroll
        for (int j=0;j<4;j++){ a1c[i][j]=0.f; a2c[i][j]=0.f; }
    const int arow = (tid&63)>>2, akc = (tid&3)<<2;
    const int wk = tid>>3, wn = (tid&7)<<3;

    for (int a=0;a<3;a++){
        const float* A1 = icb + (long)(l*3+a)*BH;
        const float* A2 = ccb + (long)(l*3+a)*BH;
        const float* W  = Wilc + (long)(l*3+a)*HH;
        for (int k0=0;k0<512;k0+=16){
            {
                const float* Ab = (tid < 64) ? A1 : A2;
                float* As = (tid < 64) ? &As1[0][0] : &As2[0][0];
                float4 v = *(const float4*)(Ab + (long)(m0+arow)*512 + k0+akc);
                As[(akc  )*16 + arow] = v.x;
                As[(akc+1)*16 + arow] = v.y;
                As[(akc+2)*16 + arow] = v.z;
                As[(akc+3)*16 + arow] = v.w;
            }
            *(float4*)&Ws[wk][wn]   = *(const float4*)(W + (long)(k0+wk)*512 + n0+wn);
            *(float4*)&Ws[wk][wn+4] = *(const float4*)(W + (long)(k0+wk)*512 + n0+wn+4);
            __syncthreads();
#pragma unroll
            for (int kk=0;kk<16;kk++){
                float2 a1 = *(const float2*)&As1[kk][ty*2];
                float2 a2 = *(const float2*)&As2[kk][ty*2];
                float4 w  = *(const float4*)&Ws[kk][tx*4];
                a1c[0][0]+=a1.x*w.x; a1c[0][1]+=a1.x*w.y; a1c[0][2]+=a1.x*w.z; a1c[0][3]+=a1.x*w.w;
                a1c[1][0]+=a1.y*w.x; a1c[1][1]+=a1.y*w.y; a1c[1][2]+=a1.y*w.z; a1c[1][3]+=a1.y*w.w;
                a2c[0][0]+=a2.x*w.x; a2c[0][1]+=a2.x*w.y; a2c[0][2]+=a2.x*w.z; a2c[0][3]+=a2.x*w.w;
                a2c[1][0]+=a2.y*w.x; a2c[1][1]+=a2.y*w.y; a2c[1][2]+=a2.y*w.z; a2c[1][3]+=a2.y*w.w;
            }
            __syncthreads();
        }
    }
#pragma unroll
    for (int i=0;i<2;i++){
        int m = m0+ty*2+i;
#pragma unroll
        for (int j=0;j<4;j++){
            int n = n0+tx*4+j;
            float bs = bilc[(long)(l*3)*512+n] + bilc[(long)(l*3+1)*512+n] + bilc[(long)(l*3+2)*512+n];
            t1s[(long)l*BH + (long)m*512 + n] = a1c[i][j] + bs;
            t2s[(long)l*BH + (long)m*512 + n] = a2c[i][j] + bs;
        }
    }
}

// comb: sigmoid(t2)*softmax(t1) -> cat[b, l*512+z]
__global__ void comb_kernel(const float* __restrict__ t1s, const float* __restrict__ t2s,
                            float* __restrict__ cat)
{
    int b = blockIdx.x, l = blockIdx.y, tid = threadIdx.x;
    const float* r1 = t1s + (long)l*BH + (long)b*512;
    const float* r2 = t2s + (long)l*BH + (long)b*512;
    float v[4];
#pragma unroll
    for (int i=0;i<4;i++) v[i] = r1[tid + i*128];
    float mx = fmaxf(fmaxf(v[0],v[1]), fmaxf(v[2],v[3]));
    __shared__ float red[128];
    red[tid] = mx; __syncthreads();
    for (int st=64; st>0; st>>=1){ if (tid<st) red[tid]=fmaxf(red[tid],red[tid+st]); __syncthreads(); }
    mx = red[0]; __syncthreads();
    float e[4], sm=0.f;
#pragma unroll
    for (int i=0;i<4;i++){ e[i]=expf(v[i]-mx); sm+=e[i]; }
    red[tid]=sm; __syncthreads();
    for (int st=64; st>0; st>>=1){ if (tid<st) red[tid]+=red[tid+st]; __syncthreads(); }
    float inv = 1.f/red[0];
#pragma unroll
    for (int i=0;i<4;i++){
        int zz = tid + i*128;
        cat[(long)b*2560 + l*512 + zz] = sigf(r2[zz]) * e[i] * inv;
    }
}

// single_li split-K partials. BM=16, BN=64, grid(8,8,4).
__global__ __launch_bounds__(128) void sl_partial(
    const float* __restrict__ cat, const float* __restrict__ Wsl, float* __restrict__ part)
{
    const int kz = blockIdx.z, m0 = blockIdx.y*16, n0 = blockIdx.x*64;
    __shared__ float As[16][16], Ws[16][64];
    const int tid = threadIdx.x, tx = tid&15, ty = tid>>4;
    float acc[2][4];
#pragma unroll
    for (int i=0;i<2;i++)
#pragma unroll
        for (int j=0;j<4;j++) acc[i][j]=0.f;
    const int arow = (tid&63)>>2, akc = (tid&3)<<2;
    const int wlm = tid>>1, wlk = (tid&1)<<3;
    const int kb = kz*640;
    for (int k0=kb;k0<kb+640;k0+=16){
        if (tid < 64){
            float4 v = *(const float4*)(cat + (long)(m0+arow)*2560 + k0+akc);
            As[akc][arow]=v.x; As[akc+1][arow]=v.y; As[akc+2][arow]=v.z; As[akc+3][arow]=v.w;
        }
        const float* wr = Wsl + (long)(n0+wlm)*2560 + k0+wlk;
        float4 u0=*(const float4*)wr, u1=*(const float4*)(wr+4);
        Ws[wlk][wlm]=u0.x; Ws[wlk+1][wlm]=u0.y; Ws[wlk+2][wlm]=u0.z; Ws[wlk+3][wlm]=u0.w;
        Ws[wlk+4][wlm]=u1.x; Ws[wlk+5][wlm]=u1.y; Ws[wlk+6][wlm]=u1.z; Ws[wlk+7][wlm]=u1.w;
        __syncthreads();
#pragma unroll
        for (int kk=0;kk<16;kk++){
            float2 a = *(const float2*)&As[kk][ty*2];
            float4 w = *(const float4*)&Ws[kk][tx*4];
            acc[0][0]+=a.x*w.x; acc[0][1]+=a.x*w.y; acc[0][2]+=a.x*w.z; acc[0][3]+=a.x*w.w;
            acc[1][0]+=a.y*w.x; acc[1][1]+=a.y*w.y; acc[1][2]+=a.y*w.z; acc[1][3]+=a.y*w.w;
        }
        __syncthreads();
    }
#pragma unroll
    for (int i=0;i<2;i++){
        int m = m0+ty*2+i;
#pragma unroll
        for (int j=0;j<4;j++)
            part[(long)kz*BH + (long)m*512 + n0+tx*4+j] = acc[i][j];
    }
}

// combine partials + bias -> h_g; fused per-step linear -> y[b]
__global__ void y_kernel(const float* __restrict__ part, const float* __restrict__ bsl,
                         float* __restrict__ hg, const float* __restrict__ wlin_t,
                         const float* __restrict__ blin_t, float* __restrict__ outp)
{
    int b = blockIdx.x, tid = threadIdx.x;
    float s = 0.f;
    for (int j=tid; j<512; j+=128){
        long idx = (long)b*512 + j;
        float h = bsl[j] + part[idx] + part[BH+idx] + part[2L*BH+idx] + part[3L*BH+idx];
        hg[idx] = h;
        s += h * wlin_t[j];
    }
    __shared__ float red[128];
    red[tid]=s; __syncthreads();
    for (int st=64; st>0; st>>=1){ if (tid<st) red[tid]+=red[tid+st]; __syncthreads(); }
    if (tid==0) outp[b] = red[0] + blin_t[0];
}

extern "C" void kernel_launch(void* const* d_in, const int* in_sizes, int n_in,
                              void* d_out, int out_size)
{
    const float* x     = (const float*)d_in[0];
    const float* Wx    = (const float*)d_in[1];
    const float* Wh    = (const float*)d_in[2];
    const float* bl    = (const float*)d_in[3];
    const float* Wg_h  = (const float*)d_in[4];
    const float* Wg_p  = (const float*)d_in[5];
    const float* bg    = (const float*)d_in[6];
    const float* Wilc  = (const float*)d_in[7];
    const float* bilc  = (const float*)d_in[8];
    const float* Wsl   = (const float*)d_in[9];
    const float* bsl   = (const float*)d_in[10];
    const float* Wlin  = (const float*)d_in[11];
    const float* blin  = (const float*)d_in[12];
    float* out = (float*)d_out;

    float *h, *c, *hg, *ic, *cc, *t1, *t2, *cat, *slp;
    cudaGetSymbolAddress((void**)&h,  g_h);
    cudaGetSymbolAddress((void**)&c,  g_c);
    cudaGetSymbolAddress((void**)&hg, g_hg);
    cudaGetSymbolAddress((void**)&ic, g_ic);
    cudaGetSymbolAddress((void**)&cc, g_cc);
    cudaGetSymbolAddress((void**)&t1, g_t1);
    cudaGetSymbolAddress((void**)&t2, g_t2);
    cudaGetSymbolAddress((void**)&cat, g_cat);
    cudaGetSymbolAddress((void**)&slp, g_slp);

    zero_kernel<<<256,256>>>(h, c, hg);

    for (int t=0; t<TT; t++){
        int p = t & 1, q = p ^ 1;
        const float* hp = h + (long)p*NLA*BH;
        float*       hq = h + (long)q*NLA*BH;
        const float* cp = c + (long)p*NLA*BH;
        float*       cq = c + (long)q*NLA*BH;
        const float* hgp = hg + (long)p*BH;
        float*       hgq = hg + (long)q*BH;

        for (int l=0; l<5; l++){
            const float* A1 = (l==0) ? (x + (long)t*BH) : (hq + (long)(l-1)*3*BH);
            long a1zs = (l==0) ? 0 : BH;
            mg16<4,true><<<dim3(16,8,3),128>>>(
                A1, a1zs, hp + (long)l*3*BH, BH,
                Wx + (long)l*4*HH, Wh + (long)l*4*HH, 5L*4*HH,
                bl + (long)l*4*HD, 5L*4*HD,
                cp + (long)l*3*BH, BH,
                hq + (long)l*3*BH, cq + (long)l*3*BH, BH);
        }
        mg16<3,false><<<dim3(16,8,15),128>>>(
            hgp, 0, hq, BH,
            Wg_h, Wg_p, 3L*HH,
            bg, 3L*HD,
            cq, BH,
            ic, cc, BH);
        t12_kernel<<<dim3(8,8,5),128>>>(ic, cc, Wilc, bilc, t1, t2);
        comb_kernel<<<dim3(128,5),128>>>(t1, t2, cat);
        sl_partial<<<dim3(8,8,4),128>>>(cat, Wsl, slp);
        y_kernel<<<128,128>>>(slp, bsl, hgq, Wlin + (long)t*HD, blin + t, out + (long)t*BSZ);
    }
}

// round 6
// speedup vs baseline: 2.2243x; 1.1323x over previous
#include <cuda_runtime.h>
#include <math.h>

#define TT 64
#define BSZ 128
#define HD 512
#define NLA 15
#define BH (BSZ*HD)
#define HH (HD*HD)

__device__ float g_h[2][NLA][BH];
__device__ float g_c[2][NLA][BH];
__device__ float g_hg[2][BH];
__device__ float g_ic[NLA][BH];
__device__ float g_cc[NLA][BH];
__device__ float g_preC[30][BSZ*1536];    // cell pre-activations, 2 ksplit x 15 (l,a)
__device__ float g_tp[30][BH];            // t1/t2 partials: zb=(2l+w)*3+a
__device__ float g_slp[5][BH];            // single_li per-level partials

__device__ __forceinline__ float sigf(float x){ return 1.0f/(1.0f+expf(-x)); }

__global__ void zero_kernel(float* h0, float* c0, float* hg0){
    int n = NLA*BH;
    for (int i = blockIdx.x*blockDim.x+threadIdx.x; i < n; i += gridDim.x*blockDim.x){
        h0[i]=0.f; c0[i]=0.f; if (i<BH) hg0[i]=0.f;
    }
}

// ---- fused LSTM level: dual-source 4-gate GEMM + gate epilogue ---------------
// grid (8 n-tiles of 64, 8 m-tiles of 16, 3 axes), 128 threads.
__global__ __launch_bounds__(128) void lstm_fused(
    const float* __restrict__ A1b, long a1zs,
    const float* __restrict__ A2b,
    const float* __restrict__ W1b, const float* __restrict__ W2b,
    const float* __restrict__ bl, int l,
    const float* __restrict__ cpb,
    float* __restrict__ hqb, float* __restrict__ cqb)
{
    const int a = blockIdx.z;
    const float* A1 = A1b + (long)a*a1zs;
    const float* A2 = A2b + (long)a*BH;
    const float* cp = cpb + (long)a*BH;
    const int m0 = blockIdx.y*16, n0 = blockIdx.x*64;

    __shared__ __align__(16) float As[16][20];
    __shared__ __align__(16) float Ws[4][16][66];

    const int tid = threadIdx.x;
    const int lane = tid&31, wrp = tid>>5;
    const int arow = tid>>2, akq = (tid&3)<<2;
    float acc[4][4][2];
#pragma unroll
    for (int g=0;g<4;g++)
#pragma unroll
        for (int i=0;i<4;i++){ acc[g][i][0]=0.f; acc[g][i][1]=0.f; }

    for (int s=0;s<2;s++){
        const float* A = s ? A2 : A1;
        const float* W = (s ? W2b : W1b) + (long)a*20*HH;
        for (int k0=0;k0<512;k0+=16){
            if (tid < 64){
                float4 v = *(const float4*)(A + (long)(m0+arow)*512 + k0+akq);
                As[akq][arow]=v.x; As[akq+1][arow]=v.y;
                As[akq+2][arow]=v.z; As[akq+3][arow]=v.w;
            }
            {
                const float* Wg = W + (long)wrp*HH;
#pragma unroll
                for (int rr=0; rr<2; rr++){
                    int row = lane + rr*32;
                    const float* wp = Wg + (long)(n0+row)*512 + k0;
                    float4 u0=*(const float4*)wp,     u1=*(const float4*)(wp+4),
                           u2=*(const float4*)(wp+8), u3=*(const float4*)(wp+12);
                    Ws[wrp][0][row]=u0.x;  Ws[wrp][1][row]=u0.y;  Ws[wrp][2][row]=u0.z;  Ws[wrp][3][row]=u0.w;
                    Ws[wrp][4][row]=u1.x;  Ws[wrp][5][row]=u1.y;  Ws[wrp][6][row]=u1.z;  Ws[wrp][7][row]=u1.w;
                    Ws[wrp][8][row]=u2.x;  Ws[wrp][9][row]=u2.y;  Ws[wrp][10][row]=u2.z; Ws[wrp][11][row]=u2.w;
                    Ws[wrp][12][row]=u3.x; Ws[wrp][13][row]=u3.y; Ws[wrp][14][row]=u3.z; Ws[wrp][15][row]=u3.w;
                }
            }
            __syncthreads();
#pragma unroll
            for (int kk=0;kk<16;kk++){
                float4 av = *(const float4*)&As[kk][wrp*4];
#pragma unroll
                for (int g=0;g<4;g++){
                    float2 w = *(const float2*)&Ws[g][kk][lane*2];
                    acc[g][0][0] += av.x*w.x; acc[g][0][1] += av.x*w.y;
                    acc[g][1][0] += av.y*w.x; acc[g][1][1] += av.y*w.y;
                    acc[g][2][0] += av.z*w.x; acc[g][2][1] += av.z*w.y;
                    acc[g][3][0] += av.w*w.x; acc[g][3][1] += av.w*w.y;
                }
            }
            __syncthreads();
        }
    }
#pragma unroll
    for (int i=0;i<4;i++){
        int m = m0 + wrp*4 + i;
#pragma unroll
        for (int j=0;j<2;j++){
            int n = n0 + lane*2 + j;
            float p[4];
#pragma unroll
            for (int g=0;g<4;g++)
                p[g] = acc[g][i][j] + bl[((long)(a*5+l)*4+g)*512 + n];
            float cn = sigf(p[1])*cp[(long)m*512+n] + sigf(p[0])*tanhf(p[2]);
            hqb[(long)a*BH + (long)m*512+n] = sigf(p[3])*tanhf(cn);
            cqb[(long)a*BH + (long)m*512+n] = cn;
        }
    }
}

// ---- generic 64x64 NT GEMM, 64 threads, 8x8 microtile, dual-source ksplit ---
__global__ __launch_bounds__(64) void gnt64(
    const float* __restrict__ A1b, long a1zs,
    const float* __restrict__ A2b, long a2zs,
    const float* __restrict__ W1b, long w1zs,
    const float* __restrict__ W2b, long w2zs,
    float* __restrict__ Cb, long czs, int ldc)
{
    const int zb = blockIdx.z;
    const int ZN = gridDim.z >> 1;
    const int ks = (zb >= ZN) ? 1 : 0;
    const int z  = zb - ks*ZN;
    const float* A = ks ? A2b + (long)z*a2zs : A1b + (long)z*a1zs;
    const float* W = ks ? W2b + (long)z*w2zs : W1b + (long)z*w1zs;
    float* C = Cb + (long)zb*czs;
    const int m0 = blockIdx.y*64, n0 = blockIdx.x*64;

    __shared__ __align__(16) float As[16][68], Ws[16][68];
    const int tid = threadIdx.x, tx = tid&7, ty = tid>>3;
    float acc[8][8];
#pragma unroll
    for (int i=0;i<8;i++)
#pragma unroll
        for (int j=0;j<8;j++) acc[i][j]=0.f;

    const int r0 = tid>>2;
    const int kq = (tid&3)<<2;

    for (int k0=0;k0<512;k0+=16){
#pragma unroll
        for (int i=0;i<4;i++){
            int row = r0 + 16*i;
            float4 v = *(const float4*)(A + (long)(m0+row)*512 + k0+kq);
            As[kq][row]=v.x; As[kq+1][row]=v.y; As[kq+2][row]=v.z; As[kq+3][row]=v.w;
            v = *(const float4*)(W + (long)(n0+row)*512 + k0+kq);
            Ws[kq][row]=v.x; Ws[kq+1][row]=v.y; Ws[kq+2][row]=v.z; Ws[kq+3][row]=v.w;
        }
        __syncthreads();
#pragma unroll
        for (int kk=0;kk<16;kk++){
            float4 a0 = *(const float4*)&As[kk][ty*8];
            float4 a1 = *(const float4*)&As[kk][ty*8+4];
            float4 w0 = *(const float4*)&Ws[kk][tx*8];
            float4 w1 = *(const float4*)&Ws[kk][tx*8+4];
            float am[8] = {a0.x,a0.y,a0.z,a0.w,a1.x,a1.y,a1.z,a1.w};
            float wn[8] = {w0.x,w0.y,w0.z,w0.w,w1.x,w1.y,w1.z,w1.w};
#pragma unroll
            for (int i=0;i<8;i++)
#pragma unroll
                for (int j=0;j<8;j++) acc[i][j] += am[i]*wn[j];
        }
        __syncthreads();
    }
#pragma unroll
    for (int i=0;i<8;i++){
        float4 o0 = {acc[i][0],acc[i][1],acc[i][2],acc[i][3]};
        float4 o1 = {acc[i][4],acc[i][5],acc[i][6],acc[i][7]};
        float* cr = C + (long)(m0+ty*8+i)*ldc + n0+tx*8;
        *(float4*)cr = o0;
        *(float4*)(cr+4) = o1;
    }
}

// ---- 64x64 NN GEMM for t12 ---------------------------------------------------
__global__ __launch_bounds__(64) void gnn64(
    const float* __restrict__ icb, const float* __restrict__ ccb,
    const float* __restrict__ Wilc, float* __restrict__ Cb)
{
    const int zb = blockIdx.z;
    const int a = zb % 3, lw = zb / 3;
    const int w = lw & 1, l = lw >> 1;
    const float* A = (w ? ccb : icb) + (long)(l*3+a)*BH;
    const float* W = Wilc + (long)(l*3+a)*HH;
    float* C = Cb + (long)zb*BH;
    const int m0 = blockIdx.y*64, n0 = blockIdx.x*64;

    __shared__ __align__(16) float As[16][68], Ws[16][68];
    const int tid = threadIdx.x, tx = tid&7, ty = tid>>3;
    float acc[8][8];
#pragma unroll
    for (int i=0;i<8;i++)
#pragma unroll
        for (int j=0;j<8;j++) acc[i][j]=0.f;

    const int r0 = tid>>2;
    const int kq = (tid&3)<<2;

    for (int k0=0;k0<512;k0+=16){
#pragma unroll
        for (int i=0;i<4;i++){
            int row = r0 + 16*i;
            float4 v = *(const float4*)(A + (long)(m0+row)*512 + k0+kq);
            As[kq][row]=v.x; As[kq+1][row]=v.y; As[kq+2][row]=v.z; As[kq+3][row]=v.w;
            int j = tid + 64*i;
            int krow = j >> 4, nq = (j & 15) << 2;
            *(float4*)&Ws[krow][nq] = *(const float4*)(W + (long)(k0+krow)*512 + n0+nq);
        }
        __syncthreads();
#pragma unroll
        for (int kk=0;kk<16;kk++){
            float4 a0 = *(const float4*)&As[kk][ty*8];
            float4 a1 = *(const float4*)&As[kk][ty*8+4];
            float4 w0 = *(const float4*)&Ws[kk][tx*8];
            float4 w1 = *(const float4*)&Ws[kk][tx*8+4];
            float am[8] = {a0.x,a0.y,a0.z,a0.w,a1.x,a1.y,a1.z,a1.w};
            float wn[8] = {w0.x,w0.y,w0.z,w0.w,w1.x,w1.y,w1.z,w1.w};
#pragma unroll
            for (int i=0;i<8;i++)
#pragma unroll
                for (int j=0;j<8;j++) acc[i][j] += am[i]*wn[j];
        }
        __syncthreads();
    }
#pragma unroll
    for (int i=0;i<8;i++){
        float4 o0 = {acc[i][0],acc[i][1],acc[i][2],acc[i][3]};
        float4 o1 = {acc[i][4],acc[i][5],acc[i][6],acc[i][7]};
        float* cr = C + (long)(m0+ty*8+i)*512 + n0+tx*8;
        *(float4*)cr = o0;
        *(float4*)(cr+4) = o1;
    }
}

// ---- cell gate epilogue: pre(2 x 15) -> ic, cc -------------------------------
__global__ void cell_gate(const float* __restrict__ pre, const float* __restrict__ bg,
                          const float* __restrict__ sc,
                          float* __restrict__ ic, float* __restrict__ cc)
{
    long idx = (long)blockIdx.x*blockDim.x + threadIdx.x;
    int z = (int)(idx >> 16);
    int r = (int)(idx & 65535);
    int m = r >> 9, n = r & 511;
    float p[3];
#pragma unroll
    for (int g=0; g<3; g++){
        long o = ((long)z*BSZ + m)*1536 + g*512 + n;
        p[g] = pre[o] + pre[(long)15*BSZ*1536 + o] + bg[((long)z*3 + g)*512 + n];
    }
    float icv = sigf(p[0]) * sc[(long)z*BH + r];
    ic[(long)z*BH + r] = icv;
    cc[(long)z*BH + r] = sigf(p[1])*tanhf(p[2]) + icv;
}

// ---- fused comb + single_li per-level partial GEMM ---------------------------
__global__ __launch_bounds__(128) void combsl(
    const float* __restrict__ tp, const float* __restrict__ bilc,
    const float* __restrict__ Wsl, float* __restrict__ part)
{
    const int l = blockIdx.z, m0 = blockIdx.y*16, n0 = blockIdx.x*64;
    __shared__ __align__(16) float s1[16][520];
    __shared__ __align__(16) float Ws[16][68];
    const int tid = threadIdx.x;
    const int row = tid>>3, ln = tid&7;
    const int b = m0 + row;

    float mx = -1e30f;
    for (int i=0;i<64;i++){
        int z = ln + i*8;
        float v1 = bilc[(long)(l*3+0)*512+z] + bilc[(long)(l*3+1)*512+z] + bilc[(long)(l*3+2)*512+z];
#pragma unroll
        for (int a=0;a<3;a++)
            v1 += tp[((long)((2*l+0)*3+a))*BH + (long)b*512 + z];
        s1[row][z] = v1;
        mx = fmaxf(mx, v1);
    }
#pragma unroll
    for (int o=4;o>0;o>>=1) mx = fmaxf(mx, __shfl_xor_sync(0xffffffffu, mx, o, 8));
    float sm = 0.f;
    for (int i=0;i<64;i++){
        int z = ln + i*8;
        float e = expf(s1[row][z] - mx);
        s1[row][z] = e; sm += e;
    }
#pragma unroll
    for (int o=4;o>0;o>>=1) sm += __shfl_xor_sync(0xffffffffu, sm, o, 8);
    float inv = 1.f/sm;
    for (int i=0;i<64;i++){
        int z = ln + i*8;
        float v2 = bilc[(long)(l*3+0)*512+z] + bilc[(long)(l*3+1)*512+z] + bilc[(long)(l*3+2)*512+z];
#pragma unroll
        for (int a=0;a<3;a++)
            v2 += tp[((long)((2*l+1)*3+a))*BH + (long)b*512 + z];
        s1[row][z] = s1[row][z] * inv * sigf(v2);
    }
    __syncthreads();

    const int tx = tid&15, ty = tid>>4;
    const int wlm = tid>>1, wlk = (tid&1)<<3;
    float acc[2][4];
#pragma unroll
    for (int i=0;i<2;i++)
#pragma unroll
        for (int j=0;j<4;j++) acc[i][j]=0.f;
    for (int k0=0;k0<512;k0+=16){
        const float* wp = Wsl + (long)(n0+wlm)*2560 + l*512 + k0+wlk;
        float4 u0=*(const float4*)wp, u1=*(const float4*)(wp+4);
        Ws[wlk][wlm]=u0.x; Ws[wlk+1][wlm]=u0.y; Ws[wlk+2][wlm]=u0.z; Ws[wlk+3][wlm]=u0.w;
        Ws[wlk+4][wlm]=u1.x; Ws[wlk+5][wlm]=u1.y; Ws[wlk+6][wlm]=u1.z; Ws[wlk+7][wlm]=u1.w;
        __syncthreads();
#pragma unroll
        for (int kk=0;kk<16;kk++){
            float a0 = s1[ty*2][k0+kk], a1 = s1[ty*2+1][k0+kk];
            float4 w = *(const float4*)&Ws[kk][tx*4];
            acc[0][0]+=a0*w.x; acc[0][1]+=a0*w.y; acc[0][2]+=a0*w.z; acc[0][3]+=a0*w.w;
            acc[1][0]+=a1*w.x; acc[1][1]+=a1*w.y; acc[1][2]+=a1*w.z; acc[1][3]+=a1*w.w;
        }
        __syncthreads();
    }
#pragma unroll
    for (int i=0;i<2;i++)
#pragma unroll
        for (int j=0;j<4;j++)
            part[(long)l*BH + (long)(m0+ty*2+i)*512 + n0+tx*4+j] = acc[i][j];
}

// ---- combine 5 level partials + bias -> h_g; fused per-step linear -> y ------
__global__ void y_kernel(const float* __restrict__ part, const float* __restrict__ bsl,
                         float* __restrict__ hg, const float* __restrict__ wlin_t,
                         const float* __restrict__ blin_t, float* __restrict__ outp)
{
    int b = blockIdx.x, tid = threadIdx.x;
    float s = 0.f;
    for (int j=tid; j<512; j+=128){
        long idx = (long)b*512 + j;
        float h = bsl[j] + part[idx] + part[BH+idx] + part[2L*BH+idx]
                + part[3L*BH+idx] + part[4L*BH+idx];
        hg[idx] = h;
        s += h * wlin_t[j];
    }
    __shared__ float red[128];
    red[tid]=s; __syncthreads();
    for (int st=64; st>0; st>>=1){ if (tid<st) red[tid]+=red[tid+st]; __syncthreads(); }
    if (tid==0) outp[b] = red[0] + blin_t[0];
}

extern "C" void kernel_launch(void* const* d_in, const int* in_sizes, int n_in,
                              void* d_out, int out_size)
{
    const float* x     = (const float*)d_in[0];
    const float* Wx    = (const float*)d_in[1];
    const float* Wh    = (const float*)d_in[2];
    const float* bl    = (const float*)d_in[3];
    const float* Wg_h  = (const float*)d_in[4];
    const float* Wg_p  = (const float*)d_in[5];
    const float* bg    = (const float*)d_in[6];
    const float* Wilc  = (const float*)d_in[7];
    const float* bilc  = (const float*)d_in[8];
    const float* Wsl   = (const float*)d_in[9];
    const float* bsl   = (const float*)d_in[10];
    const float* Wlin  = (const float*)d_in[11];
    const float* blin  = (const float*)d_in[12];
    float* out = (float*)d_out;

    float *h, *c, *hg, *ic, *cc, *preC, *tp, *slp;
    cudaGetSymbolAddress((void**)&h,   g_h);
    cudaGetSymbolAddress((void**)&c,   g_c);
    cudaGetSymbolAddress((void**)&hg,  g_hg);
    cudaGetSymbolAddress((void**)&ic,  g_ic);
    cudaGetSymbolAddress((void**)&cc,  g_cc);
    cudaGetSymbolAddress((void**)&preC, g_preC);
    cudaGetSymbolAddress((void**)&tp,  g_tp);
    cudaGetSymbolAddress((void**)&slp, g_slp);

    zero_kernel<<<256,256>>>(h, c, hg);

    for (int t=0; t<TT; t++){
        int p = t & 1, q = p ^ 1;
        const float* hp = h + (long)p*NLA*BH;
        float*       hq = h + (long)q*NLA*BH;
        const float* cp = c + (long)p*NLA*BH;
        float*       cq = c + (long)q*NLA*BH;
        const float* hgp = hg + (long)p*BH;
        float*       hgq = hg + (long)q*BH;

        for (int l=0; l<5; l++){
            const float* A1 = (l==0) ? (x + (long)t*BH) : (hq + (long)(l-1)*3*BH);
            long a1zs = (l==0) ? 0 : BH;
            lstm_fused<<<dim3(8,8,3),128>>>(
                A1, a1zs, hp + (long)l*3*BH,
                Wx + (long)l*4*HH, Wh + (long)l*4*HH,
                bl, l,
                cp + (long)l*3*BH,
                hq + (long)l*3*BH, cq + (long)l*3*BH);
        }
        gnt64<<<dim3(24,2,30),64>>>(
            hgp, 0, hq, BH,
            Wg_h, 3L*HH, Wg_p, 3L*HH,
            preC, (long)BSZ*1536, 1536);
        cell_gate<<<3840,256>>>(preC, bg, cq, ic, cc);
        gnn64<<<dim3(8,2,30),64>>>(ic, cc, Wilc, tp);
        combsl<<<dim3(8,8,5),128>>>(tp, bilc, Wsl, slp);
        y_kernel<<<128,128>>>(slp, bsl, hgq, Wlin + (long)t*HD, blin + t, out + (long)t*BSZ);
    }
}

// round 7
// speedup vs baseline: 4.0536x; 1.8224x over previous
#include <cuda_runtime.h>
#include <cuda_bf16.h>
#include <math.h>
#include <stdint.h>

#define TT 64
#define BSZ 128
#define HD 512
#define NLA 15
#define BH (BSZ*HD)
#define HH (HD*HD)
#define NWL (3L*5*4*512*512)   // LSTM weight element count per matrix

__device__ float g_h[2][NLA][BH];
__device__ float g_c[2][NLA][BH];
__device__ float g_hg[2][BH];
__device__ float g_ic[NLA][BH];
__device__ float g_cc[NLA][BH];
__device__ float g_preC[30][BSZ*1536];
__device__ float g_tp[30][BH];
__device__ float g_slp[5][BH];

// split-bf16 weight/activation buffers
__device__ __nv_bfloat16 g_Wxhi[NWL], g_Wxlo[NWL], g_Whhi[NWL], g_Whlo[NWL];
__device__ __nv_bfloat16 g_xh[(long)TT*BH], g_xl[(long)TT*BH];
__device__ __nv_bfloat16 g_hbh[2][NLA][BH], g_hbl[2][NLA][BH];

__device__ __forceinline__ float sigf(float x){ return 1.0f/(1.0f+expf(-x)); }

__global__ void zero_kernel(float* h0, float* c0, float* hg0,
                            __nv_bfloat16* hbh0, __nv_bfloat16* hbl0){
    int n = NLA*BH;
    __nv_bfloat16 z = __float2bfloat16(0.f);
    for (int i = blockIdx.x*blockDim.x+threadIdx.x; i < n; i += gridDim.x*blockDim.x){
        h0[i]=0.f; c0[i]=0.f; hbh0[i]=z; hbl0[i]=z; if (i<BH) hg0[i]=0.f;
    }
}

__global__ void conv_w_lstm(const float* __restrict__ Wx, const float* __restrict__ Wh,
    __nv_bfloat16* xh, __nv_bfloat16* xl, __nv_bfloat16* hh, __nv_bfloat16* hl){
    for (long i = (long)blockIdx.x*blockDim.x+threadIdx.x; i < NWL;
         i += (long)gridDim.x*blockDim.x){
        float w = Wx[i];
        __nv_bfloat16 hi = __float2bfloat16(w);
        xh[i] = hi; xl[i] = __float2bfloat16(w - __bfloat162float(hi));
        w = Wh[i];
        hi = __float2bfloat16(w);
        hh[i] = hi; hl[i] = __float2bfloat16(w - __bfloat162float(hi));
    }
}

__global__ void conv_x(const float* __restrict__ x, __nv_bfloat16* xh, __nv_bfloat16* xl){
    const long N = (long)TT*BH;
    for (long i = (long)blockIdx.x*blockDim.x+threadIdx.x; i < N;
         i += (long)gridDim.x*blockDim.x){
        float w = x[i];
        __nv_bfloat16 hi = __float2bfloat16(w);
        xh[i] = hi; xl[i] = __float2bfloat16(w - __bfloat162float(hi));
    }
}

__device__ __forceinline__ void ldsm4(uint32_t addr, uint32_t &r0, uint32_t &r1,
                                      uint32_t &r2, uint32_t &r3){
    asm volatile("ldmatrix.sync.aligned.m8n8.x4.shared.b16 {%0,%1,%2,%3}, [%4];"
        : "=r"(r0),"=r"(r1),"=r"(r2),"=r"(r3) : "r"(addr));
}
__device__ __forceinline__ void mma16816(float* c, const uint32_t* a,
                                         uint32_t b0, uint32_t b1){
    asm volatile("mma.sync.aligned.m16n8k16.row.col.f32.bf16.bf16.f32 "
        "{%0,%1,%2,%3},{%4,%5,%6,%7},{%8,%9},{%0,%1,%2,%3};"
        : "+f"(c[0]),"+f"(c[1]),"+f"(c[2]),"+f"(c[3])
        : "r"(a[0]),"r"(a[1]),"r"(a[2]),"r"(a[3]),"r"(b0),"r"(b1));
}

// ---- LSTM level via split-bf16 tensor-core GEMM + fused gate epilogue --------
// grid (8 n-tiles[64/gate], 4 m-tiles[32], 3 axes), 256 threads (8 warps).
// warp w: gate = w>>1, n-offset (w&1)*32. 3 passes: ahi*whi + ahi*wlo + alo*whi.
__global__ __launch_bounds__(256) void lstm_mma(
    const __nv_bfloat16* __restrict__ A1h, const __nv_bfloat16* __restrict__ A1l, long a1zs,
    const __nv_bfloat16* __restrict__ A2h, const __nv_bfloat16* __restrict__ A2l,
    const __nv_bfloat16* __restrict__ W1h, const __nv_bfloat16* __restrict__ W1l,
    const __nv_bfloat16* __restrict__ W2h, const __nv_bfloat16* __restrict__ W2l,
    const float* __restrict__ bl, int l, const float* __restrict__ cpb,
    float* __restrict__ hqb, float* __restrict__ cqb,
    __nv_bfloat16* __restrict__ hbhq, __nv_bfloat16* __restrict__ hblq)
{
    const int a = blockIdx.z;
    const int m0 = blockIdx.y*32, n0 = blockIdx.x*64;
    const int tid = threadIdx.x, lane = tid&31, wid = tid>>5;
    const int g = wid>>1, nb = (wid&1)*32;

    __shared__ __align__(16) __nv_bfloat16 sA[2][32][40];
    __shared__ __align__(16) __nv_bfloat16 sW[2][4][64][40];

    float C[2][4][4];
#pragma unroll
    for (int mh=0;mh<2;mh++)
#pragma unroll
        for (int f=0;f<4;f++)
#pragma unroll
            for (int r=0;r<4;r++) C[mh][f][r]=0.f;

    const __nv_bfloat16* Ah[2] = {A1h + (long)a*a1zs, A2h + (long)a*BH};
    const __nv_bfloat16* Al[2] = {A1l + (long)a*a1zs, A2l + (long)a*BH};
    const __nv_bfloat16* Wp[2][2] = {
        {W1h + (long)a*20*HH, W1l + (long)a*20*HH},
        {W2h + (long)a*20*HH, W2l + (long)a*20*HH}};

    const uint32_t sA_base = (uint32_t)__cvta_generic_to_shared(&sA[0][0][0]);
    const uint32_t sW_base = (uint32_t)__cvta_generic_to_shared(&sW[0][0][0][0]);

    // LDSM lane address components
    const int a_row = lane&15, a_ko = (lane>>4)*8;
    const int b_r = lane&7, b_sel = lane>>3;
    const int b_rowoff = b_r + ((b_sel>>1)?8:0), b_ko = (b_sel&1)*8;

    const int lq = tid&3, lm = (tid>>2)&31, lhl = tid>>7;  // A-load role

    for (int s=0;s<2;s++){
        const __nv_bfloat16* Asrc[2] = {Ah[s], Al[s]};
        for (int kc=0;kc<16;kc++){
            const int k0 = kc*32;
            {   // A chunk: 2(hl) x 32m x 32k, one float4 per thread
                const __nv_bfloat16* src = Asrc[lhl] + (long)(m0+lm)*512 + k0 + lq*8;
                *(float4*)&sA[lhl][lm][lq*8] = *(const float4*)src;
            }
#pragma unroll
            for (int it=0; it<8; it++){   // W chunk: 2 x 4g x 64n x 32k
                int idx = tid + it*256;
                int q = idx&3, n = (idx>>2)&63, gg = (idx>>8)&3, hl = (idx>>10)&1;
                const __nv_bfloat16* src = Wp[s][hl] + (long)gg*HH
                                         + (long)(n0+n)*512 + k0 + q*8;
                *(float4*)&sW[hl][gg][n][q*8] = *(const float4*)src;
            }
            __syncthreads();
#pragma unroll
            for (int kf=0;kf<2;kf++){
                uint32_t ahf[2][4], alf[2][4];
#pragma unroll
                for (int mh=0;mh<2;mh++){
                    uint32_t ad = sA_base + (uint32_t)(((mh*16 + a_row)*40 + kf*16 + a_ko)*2);
                    ldsm4(ad, ahf[mh][0], ahf[mh][1], ahf[mh][2], ahf[mh][3]);
                    ad += 32*40*2;
                    ldsm4(ad, alf[mh][0], alf[mh][1], alf[mh][2], alf[mh][3]);
                }
#pragma unroll
                for (int nh=0; nh<2; nh++){
                    int row = nb + nh*16 + b_rowoff;
                    uint32_t wd = sW_base + (uint32_t)((((g*64) + row)*40 + kf*16 + b_ko)*2);
                    uint32_t bh0,bh1,bh2,bh3, bl0,bl1,bl2,bl3;
                    ldsm4(wd, bh0,bh1,bh2,bh3);
                    ldsm4(wd + 4*64*40*2, bl0,bl1,bl2,bl3);
#pragma unroll
                    for (int mh=0;mh<2;mh++){
                        mma16816(C[mh][nh*2+0], ahf[mh], bh0, bh1);
                        mma16816(C[mh][nh*2+1], ahf[mh], bh2, bh3);
                        mma16816(C[mh][nh*2+0], ahf[mh], bl0, bl1);
                        mma16816(C[mh][nh*2+1], ahf[mh], bl2, bl3);
                        mma16816(C[mh][nh*2+0], alf[mh], bh0, bh1);
                        mma16816(C[mh][nh*2+1], alf[mh], bh2, bh3);
                    }
                }
            }
            __syncthreads();
        }
    }

    // epilogue: exchange 4 gates through smem (reuse sW region: [4][32][64] f32)
    float* preS = (float*)&sW[0][0][0][0];
    {
        int r = lane>>2, i2 = (lane&3)*2;
#pragma unroll
        for (int mh=0;mh<2;mh++)
#pragma unroll
            for (int f=0;f<4;f++){
                int mrow = mh*16 + r;
                int ncol = nb + f*8 + i2;
                preS[(g*32 + mrow)*64 + ncol]     = C[mh][f][0];
                preS[(g*32 + mrow)*64 + ncol+1]   = C[mh][f][1];
                preS[(g*32 + mrow+8)*64 + ncol]   = C[mh][f][2];
                preS[(g*32 + mrow+8)*64 + ncol+1] = C[mh][f][3];
            }
    }
    __syncthreads();
    {
        const float* cp = cpb + (long)a*BH;
        int m = tid>>3, nn = (tid&7)*8;
#pragma unroll
        for (int j=0;j<8;j++){
            int n = nn + j;
            int gn = n0 + n;
            float p[4];
#pragma unroll
            for (int gg=0;gg<4;gg++)
                p[gg] = preS[(gg*32+m)*64 + n] + bl[((long)(a*5+l)*4+gg)*512 + gn];
            long o = (long)a*BH + (long)(m0+m)*512 + gn;
            float cn = sigf(p[1])*cp[(long)(m0+m)*512+gn] + sigf(p[0])*tanhf(p[2]);
            float hv = sigf(p[3])*tanhf(cn);
            hqb[o] = hv; cqb[o] = cn;
            __nv_bfloat16 hh = __float2bfloat16(hv);
            hbhq[o] = hh;
            hblq[o] = __float2bfloat16(hv - __bfloat162float(hh));
        }
    }
}

// ---- generic 64x64 NT GEMM, 64 threads, 8x8 microtile, dual-source ksplit ---
__global__ __launch_bounds__(64) void gnt64(
    const float* __restrict__ A1b, long a1zs,
    const float* __restrict__ A2b, long a2zs,
    const float* __restrict__ W1b, long w1zs,
    const float* __restrict__ W2b, long w2zs,
    float* __restrict__ Cb, long czs, int ldc)
{
    const int zb = blockIdx.z;
    const int ZN = gridDim.z >> 1;
    const int ks = (zb >= ZN) ? 1 : 0;
    const int z  = zb - ks*ZN;
    const float* A = ks ? A2b + (long)z*a2zs : A1b + (long)z*a1zs;
    const float* W = ks ? W2b + (long)z*w2zs : W1b + (long)z*w1zs;
    float* C = Cb + (long)zb*czs;
    const int m0 = blockIdx.y*64, n0 = blockIdx.x*64;

    __shared__ __align__(16) float As[16][68], Ws[16][68];
    const int tid = threadIdx.x, tx = tid&7, ty = tid>>3;
    float acc[8][8];
#pragma unroll
    for (int i=0;i<8;i++)
#pragma unroll
        for (int j=0;j<8;j++) acc[i][j]=0.f;

    const int r0 = tid>>2;
    const int kq = (tid&3)<<2;

    for (int k0=0;k0<512;k0+=16){
#pragma unroll
        for (int i=0;i<4;i++){
            int row = r0 + 16*i;
            float4 v = *(const float4*)(A + (long)(m0+row)*512 + k0+kq);
            As[kq][row]=v.x; As[kq+1][row]=v.y; As[kq+2][row]=v.z; As[kq+3][row]=v.w;
            v = *(const float4*)(W + (long)(n0+row)*512 + k0+kq);
            Ws[kq][row]=v.x; Ws[kq+1][row]=v.y; Ws[kq+2][row]=v.z; Ws[kq+3][row]=v.w;
        }
        __syncthreads();
#pragma unroll
        for (int kk=0;kk<16;kk++){
            float4 a0 = *(const float4*)&As[kk][ty*8];
            float4 a1 = *(const float4*)&As[kk][ty*8+4];
            float4 w0 = *(const float4*)&Ws[kk][tx*8];
            float4 w1 = *(const float4*)&Ws[kk][tx*8+4];
            float am[8] = {a0.x,a0.y,a0.z,a0.w,a1.x,a1.y,a1.z,a1.w};
            float wn[8] = {w0.x,w0.y,w0.z,w0.w,w1.x,w1.y,w1.z,w1.w};
#pragma unroll
            for (int i=0;i<8;i++)
#pragma unroll
                for (int j=0;j<8;j++) acc[i][j] += am[i]*wn[j];
        }
        __syncthreads();
    }
#pragma unroll
    for (int i=0;i<8;i++){
        float4 o0 = {acc[i][0],acc[i][1],acc[i][2],acc[i][3]};
        float4 o1 = {acc[i][4],acc[i][5],acc[i][6],acc[i][7]};
        float* cr = C + (long)(m0+ty*8+i)*ldc + n0+tx*8;
        *(float4*)cr = o0;
        *(float4*)(cr+4) = o1;
    }
}

// ---- 64x64 NN GEMM for t12 ---------------------------------------------------
__global__ __launch_bounds__(64) void gnn64(
    const float* __restrict__ icb, const float* __restrict__ ccb,
    const float* __restrict__ Wilc, float* __restrict__ Cb)
{
    const int zb = blockIdx.z;
    const int a = zb % 3, lw = zb / 3;
    const int w = lw & 1, l = lw >> 1;
    const float* A = (w ? ccb : icb) + (long)(l*3+a)*BH;
    const float* W = Wilc + (long)(l*3+a)*HH;
    float* C = Cb + (long)zb*BH;
    const int m0 = blockIdx.y*64, n0 = blockIdx.x*64;

    __shared__ __align__(16) float As[16][68], Ws[16][68];
    const int tid = threadIdx.x, tx = tid&7, ty = tid>>3;
    float acc[8][8];
#pragma unroll
    for (int i=0;i<8;i++)
#pragma unroll
        for (int j=0;j<8;j++) acc[i][j]=0.f;

    const int r0 = tid>>2;
    const int kq = (tid&3)<<2;

    for (int k0=0;k0<512;k0+=16){
#pragma unroll
        for (int i=0;i<4;i++){
            int row = r0 + 16*i;
            float4 v = *(const float4*)(A + (long)(m0+row)*512 + k0+kq);
            As[kq][row]=v.x; As[kq+1][row]=v.y; As[kq+2][row]=v.z; As[kq+3][row]=v.w;
            int j = tid + 64*i;
            int krow = j >> 4, nq = (j & 15) << 2;
            *(float4*)&Ws[krow][nq] = *(const float4*)(W + (long)(k0+krow)*512 + n0+nq);
        }
        __syncthreads();
#pragma unroll
        for (int kk=0;kk<16;kk++){
            float4 a0 = *(const float4*)&As[kk][ty*8];
            float4 a1 = *(const float4*)&As[kk][ty*8+4];
            float4 w0 = *(const float4*)&Ws[kk][tx*8];
            float4 w1 = *(const float4*)&Ws[kk][tx*8+4];
            float am[8] = {a0.x,a0.y,a0.z,a0.w,a1.x,a1.y,a1.z,a1.w};
            float wn[8] = {w0.x,w0.y,w0.z,w0.w,w1.x,w1.y,w1.z,w1.w};
#pragma unroll
            for (int i=0;i<8;i++)
#pragma unroll
                for (int j=0;j<8;j++) acc[i][j] += am[i]*wn[j];
        }
        __syncthreads();
    }
#pragma unroll
    for (int i=0;i<8;i++){
        float4 o0 = {acc[i][0],acc[i][1],acc[i][2],acc[i][3]};
        float4 o1 = {acc[i][4],acc[i][5],acc[i][6],acc[i][7]};
        float* cr = C + (long)(m0+ty*8+i)*512 + n0+tx*8;
        *(float4*)cr = o0;
        *(float4*)(cr+4) = o1;
    }
}

// ---- cell gate epilogue ------------------------------------------------------
__global__ void cell_gate(const float* __restrict__ pre, const float* __restrict__ bg,
                          const float* __restrict__ sc,
                          float* __restrict__ ic, float* __restrict__ cc)
{
    long idx = (long)blockIdx.x*blockDim.x + threadIdx.x;
    int z = (int)(idx >> 16);
    int r = (int)(idx & 65535);
    int m = r >> 9, n = r & 511;
    float p[3];
#pragma unroll
    for (int g=0; g<3; g++){
        long o = ((long)z*BSZ + m)*1536 + g*512 + n;
        p[g] = pre[o] + pre[(long)15*BSZ*1536 + o] + bg[((long)z*3 + g)*512 + n];
    }
    float icv = sigf(p[0]) * sc[(long)z*BH + r];
    ic[(long)z*BH + r] = icv;
    cc[(long)z*BH + r] = sigf(p[1])*tanhf(p[2]) + icv;
}

// ---- fused comb + single_li per-level partial GEMM ---------------------------
__global__ __launch_bounds__(128) void combsl(
    const float* __restrict__ tp, const float* __restrict__ bilc,
    const float* __restrict__ Wsl, float* __restrict__ part)
{
    const int l = blockIdx.z, m0 = blockIdx.y*16, n0 = blockIdx.x*64;
    __shared__ __align__(16) float s1[16][520];
    __shared__ __align__(16) float Ws[16][68];
    const int tid = threadIdx.x;
    const int row = tid>>3, ln = tid&7;
    const int b = m0 + row;

    float mx = -1e30f;
    for (int i=0;i<64;i++){
        int z = ln + i*8;
        float v1 = bilc[(long)(l*3+0)*512+z] + bilc[(long)(l*3+1)*512+z] + bilc[(long)(l*3+2)*512+z];
#pragma unroll
        for (int a=0;a<3;a++)
            v1 += tp[((long)((2*l+0)*3+a))*BH + (long)b*512 + z];
        s1[row][z] = v1;
        mx = fmaxf(mx, v1);
    }
#pragma unroll
    for (int o=4;o>0;o>>=1) mx = fmaxf(mx, __shfl_xor_sync(0xffffffffu, mx, o, 8));
    float sm = 0.f;
    for (int i=0;i<64;i++){
        int z = ln + i*8;
        float e = expf(s1[row][z] - mx);
        s1[row][z] = e; sm += e;
    }
#pragma unroll
    for (int o=4;o>0;o>>=1) sm += __shfl_xor_sync(0xffffffffu, sm, o, 8);
    float inv = 1.f/sm;
    for (int i=0;i<64;i++){
        int z = ln + i*8;
        float v2 = bilc[(long)(l*3+0)*512+z] + bilc[(long)(l*3+1)*512+z] + bilc[(long)(l*3+2)*512+z];
#pragma unroll
        for (int a=0;a<3;a++)
            v2 += tp[((long)((2*l+1)*3+a))*BH + (long)b*512 + z];
        s1[row][z] = s1[row][z] * inv * sigf(v2);
    }
    __syncthreads();

    const int tx = tid&15, ty = tid>>4;
    const int wlm = tid>>1, wlk = (tid&1)<<3;
    float acc[2][4];
#pragma unroll
    for (int i=0;i<2;i++)
#pragma unroll
        for (int j=0;j<4;j++) acc[i][j]=0.f;
    for (int k0=0;k0<512;k0+=16){
        const float* wp = Wsl + (long)(n0+wlm)*2560 + l*512 + k0+wlk;
        float4 u0=*(const float4*)wp, u1=*(const float4*)(wp+4);
        Ws[wlk][wlm]=u0.x; Ws[wlk+1][wlm]=u0.y; Ws[wlk+2][wlm]=u0.z; Ws[wlk+3][wlm]=u0.w;
        Ws[wlk+4][wlm]=u1.x; Ws[wlk+5][wlm]=u1.y; Ws[wlk+6][wlm]=u1.z; Ws[wlk+7][wlm]=u1.w;
        __syncthreads();
#pragma unroll
        for (int kk=0;kk<16;kk++){
            float a0 = s1[ty*2][k0+kk], a1 = s1[ty*2+1][k0+kk];
            float4 w = *(const float4*)&Ws[kk][tx*4];
            acc[0][0]+=a0*w.x; acc[0][1]+=a0*w.y; acc[0][2]+=a0*w.z; acc[0][3]+=a0*w.w;
            acc[1][0]+=a1*w.x; acc[1][1]+=a1*w.y; acc[1][2]+=a1*w.z; acc[1][3]+=a1*w.w;
        }
        __syncthreads();
    }
#pragma unroll
    for (int i=0;i<2;i++)
#pragma unroll
        for (int j=0;j<4;j++)
            part[(long)l*BH + (long)(m0+ty*2+i)*512 + n0+tx*4+j] = acc[i][j];
}

// ---- combine 5 level partials + bias -> h_g; fused per-step linear -> y ------
__global__ void y_kernel(const float* __restrict__ part, const float* __restrict__ bsl,
                         float* __restrict__ hg, const float* __restrict__ wlin_t,
                         const float* __restrict__ blin_t, float* __restrict__ outp)
{
    int b = blockIdx.x, tid = threadIdx.x;
    float s = 0.f;
    for (int j=tid; j<512; j+=128){
        long idx = (long)b*512 + j;
        float h = bsl[j] + part[idx] + part[BH+idx] + part[2L*BH+idx]
                + part[3L*BH+idx] + part[4L*BH+idx];
        hg[idx] = h;
        s += h * wlin_t[j];
    }
    __shared__ float red[128];
    red[tid]=s; __syncthreads();
    for (int st=64; st>0; st>>=1){ if (tid<st) red[tid]+=red[tid+st]; __syncthreads(); }
    if (tid==0) outp[b] = red[0] + blin_t[0];
}

extern "C" void kernel_launch(void* const* d_in, const int* in_sizes, int n_in,
                              void* d_out, int out_size)
{
    const float* x     = (const float*)d_in[0];
    const float* Wx    = (const float*)d_in[1];
    const float* Wh    = (const float*)d_in[2];
    const float* bl    = (const float*)d_in[3];
    const float* Wg_h  = (const float*)d_in[4];
    const float* Wg_p  = (const float*)d_in[5];
    const float* bg    = (const float*)d_in[6];
    const float* Wilc  = (const float*)d_in[7];
    const float* bilc  = (const float*)d_in[8];
    const float* Wsl   = (const float*)d_in[9];
    const float* bsl   = (const float*)d_in[10];
    const float* Wlin  = (const float*)d_in[11];
    const float* blin  = (const float*)d_in[12];
    float* out = (float*)d_out;

    float *h, *c, *hg, *ic, *cc, *preC, *tp, *slp;
    __nv_bfloat16 *wxh, *wxl, *whh, *whl, *xh, *xl, *hbh, *hbl;
    cudaGetSymbolAddress((void**)&h,   g_h);
    cudaGetSymbolAddress((void**)&c,   g_c);
    cudaGetSymbolAddress((void**)&hg,  g_hg);
    cudaGetSymbolAddress((void**)&ic,  g_ic);
    cudaGetSymbolAddress((void**)&cc,  g_cc);
    cudaGetSymbolAddress((void**)&preC, g_preC);
    cudaGetSymbolAddress((void**)&tp,  g_tp);
    cudaGetSymbolAddress((void**)&slp, g_slp);
    cudaGetSymbolAddress((void**)&wxh, g_Wxhi);
    cudaGetSymbolAddress((void**)&wxl, g_Wxlo);
    cudaGetSymbolAddress((void**)&whh, g_Whhi);
    cudaGetSymbolAddress((void**)&whl, g_Whlo);
    cudaGetSymbolAddress((void**)&xh,  g_xh);
    cudaGetSymbolAddress((void**)&xl,  g_xl);
    cudaGetSymbolAddress((void**)&hbh, g_hbh);
    cudaGetSymbolAddress((void**)&hbl, g_hbl);

    conv_w_lstm<<<1024,256>>>(Wx, Wh, wxh, wxl, whh, whl);
    conv_x<<<512,256>>>(x, xh, xl);
    zero_kernel<<<256,256>>>(h, c, hg, hbh, hbl);

    for (int t=0; t<TT; t++){
        int p = t & 1, q = p ^ 1;
        const float* hp = h + (long)p*NLA*BH;
        float*       hq = h + (long)q*NLA*BH;
        const float* cp = c + (long)p*NLA*BH;
        float*       cq = c + (long)q*NLA*BH;
        const float* hgp = hg + (long)p*BH;
        float*       hgq = hg + (long)q*BH;
        const __nv_bfloat16* hbhp = hbh + (long)p*NLA*BH;
        __nv_bfloat16*       hbhq = hbh + (long)q*NLA*BH;
        const __nv_bfloat16* hblp = hbl + (long)p*NLA*BH;
        __nv_bfloat16*       hblq = hbl + (long)q*NLA*BH;

        for (int l=0; l<5; l++){
            const __nv_bfloat16 *A1h_, *A1l_;
            long a1zs;
            if (l==0){ A1h_ = xh + (long)t*BH; A1l_ = xl + (long)t*BH; a1zs = 0; }
            else { A1h_ = hbhq + (long)(l-1)*3*BH; A1l_ = hblq + (long)(l-1)*3*BH; a1zs = BH; }
            lstm_mma<<<dim3(8,4,3),256>>>(
                A1h_, A1l_, a1zs,
                hbhp + (long)l*3*BH, hblp + (long)l*3*BH,
                wxh + (long)l*4*HH, wxl + (long)l*4*HH,
                whh + (long)l*4*HH, whl + (long)l*4*HH,
                bl, l, cp + (long)l*3*BH,
                hq + (long)l*3*BH, cq + (long)l*3*BH,
                hbhq + (long)l*3*BH, hblq + (long)l*3*BH);
        }
        gnt64<<<dim3(24,2,30),64>>>(
            hgp, 0, hq, BH,
            Wg_h, 3L*HH, Wg_p, 3L*HH,
            preC, (long)BSZ*1536, 1536);
        cell_gate<<<3840,256>>>(preC, bg, cq, ic, cc);
        gnn64<<<dim3(8,2,30),64>>>(ic, cc, Wilc, tp);
        combsl<<<dim3(8,8,5),128>>>(tp, bilc, Wsl, slp);
        y_kernel<<<128,128>>>(slp, bsl, hgq, Wlin + (long)t*HD, blin + t, out + (long)t*BSZ);
    }
}

// round 8
// speedup vs baseline: 4.5435x; 1.1209x over previous
#include <cuda_runtime.h>
#include <cuda_bf16.h>
#include <math.h>
#include <stdint.h>

#define TT 64
#define BSZ 128
#define HD 512
#define NLA 15
#define BH (BSZ*HD)
#define HH (HD*HD)
#define NWL (3L*5*4*512*512)
#define NWG (5L*3*3*512*512)

__device__ float g_c[2][NLA][BH];
__device__ float g_ic[NLA][BH];
__device__ float g_cc[NLA][BH];
__device__ float g_tp[30][BH];
__device__ float g_slp[5][BH];

__device__ __nv_bfloat16 g_Wxhi[NWL], g_Wxlo[NWL], g_Whhi[NWL], g_Whlo[NWL];
__device__ __nv_bfloat16 g_Wghh[NWG], g_Wghl[NWG], g_Wgph[NWG], g_Wgpl[NWG];
__device__ __nv_bfloat16 g_xh[(long)TT*BH], g_xl[(long)TT*BH];
__device__ __nv_bfloat16 g_hbh[2][NLA][BH], g_hbl[2][NLA][BH];
__device__ __nv_bfloat16 g_hgh[2][BH], g_hgl[2][BH];

__device__ __forceinline__ float sigf(float x){ return 1.0f/(1.0f+expf(-x)); }

__global__ void zero_kernel(float* c0, __nv_bfloat16* hbh0, __nv_bfloat16* hbl0,
                            __nv_bfloat16* hgh0, __nv_bfloat16* hgl0){
    int n = NLA*BH;
    __nv_bfloat16 z = __float2bfloat16(0.f);
    for (int i = blockIdx.x*blockDim.x+threadIdx.x; i < n; i += gridDim.x*blockDim.x){
        c0[i]=0.f; hbh0[i]=z; hbl0[i]=z;
        if (i<BH){ hgh0[i]=z; hgl0[i]=z; }
    }
}

__global__ void conv_w_lstm(const float* __restrict__ Wx, const float* __restrict__ Wh,
    __nv_bfloat16* xh, __nv_bfloat16* xl, __nv_bfloat16* hh, __nv_bfloat16* hl){
    for (long i = (long)blockIdx.x*blockDim.x+threadIdx.x; i < NWL;
         i += (long)gridDim.x*blockDim.x){
        float w = Wx[i];
        __nv_bfloat16 hi = __float2bfloat16(w);
        xh[i] = hi; xl[i] = __float2bfloat16(w - __bfloat162float(hi));
        w = Wh[i];
        hi = __float2bfloat16(w);
        hh[i] = hi; hl[i] = __float2bfloat16(w - __bfloat162float(hi));
    }
}

__global__ void conv_wg(const float* __restrict__ Gh, const float* __restrict__ Gp,
    __nv_bfloat16* ghh, __nv_bfloat16* ghl, __nv_bfloat16* gph, __nv_bfloat16* gpl){
    for (long i = (long)blockIdx.x*blockDim.x+threadIdx.x; i < NWG;
         i += (long)gridDim.x*blockDim.x){
        float w = Gh[i];
        __nv_bfloat16 hi = __float2bfloat16(w);
        ghh[i] = hi; ghl[i] = __float2bfloat16(w - __bfloat162float(hi));
        w = Gp[i];
        hi = __float2bfloat16(w);
        gph[i] = hi; gpl[i] = __float2bfloat16(w - __bfloat162float(hi));
    }
}

__global__ void conv_x(const float* __restrict__ x, __nv_bfloat16* xh, __nv_bfloat16* xl){
    const long N = (long)TT*BH;
    for (long i = (long)blockIdx.x*blockDim.x+threadIdx.x; i < N;
         i += (long)gridDim.x*blockDim.x){
        float w = x[i];
        __nv_bfloat16 hi = __float2bfloat16(w);
        xh[i] = hi; xl[i] = __float2bfloat16(w - __bfloat162float(hi));
    }
}

__device__ __forceinline__ void ldsm4(uint32_t addr, uint32_t &r0, uint32_t &r1,
                                      uint32_t &r2, uint32_t &r3){
    asm volatile("ldmatrix.sync.aligned.m8n8.x4.shared.b16 {%0,%1,%2,%3}, [%4];"
        : "=r"(r0),"=r"(r1),"=r"(r2),"=r"(r3) : "r"(addr));
}
__device__ __forceinline__ void mma16816(float* c, const uint32_t* a,
                                         uint32_t b0, uint32_t b1){
    asm volatile("mma.sync.aligned.m16n8k16.row.col.f32.bf16.bf16.f32 "
        "{%0,%1,%2,%3},{%4,%5,%6,%7},{%8,%9},{%0,%1,%2,%3};"
        : "+f"(c[0]),"+f"(c[1]),"+f"(c[2]),"+f"(c[3])
        : "r"(a[0]),"r"(a[1]),"r"(a[2]),"r"(a[3]),"r"(b0),"r"(b1));
}
__device__ __forceinline__ void cpa16(uint32_t dst, const void* src){
    asm volatile("cp.async.ca.shared.global [%0], [%1], 16;" :: "r"(dst), "l"(src));
}
__device__ __forceinline__ void cpa_commit(){ asm volatile("cp.async.commit_group;"); }

// ---- LSTM level: pipelined split-bf16 mma + fused gate epilogue --------------
// grid (16 n-tiles[32/gate], 4 m-tiles[32], 3 axes) = 192 blocks, 256 thr.
__global__ __launch_bounds__(256) void lstm_mma(
    const __nv_bfloat16* __restrict__ A1h, const __nv_bfloat16* __restrict__ A1l, long a1zs,
    const __nv_bfloat16* __restrict__ A2h, const __nv_bfloat16* __restrict__ A2l,
    const __nv_bfloat16* __restrict__ W1h, const __nv_bfloat16* __restrict__ W1l,
    const __nv_bfloat16* __restrict__ W2h, const __nv_bfloat16* __restrict__ W2l,
    const float* __restrict__ bl, int l, const float* __restrict__ cpb,
    float* __restrict__ cqb,
    __nv_bfloat16* __restrict__ hbhq, __nv_bfloat16* __restrict__ hblq)
{
    const int a = blockIdx.z;
    const int m0 = blockIdx.y*32, n0 = blockIdx.x*32;
    const int tid = threadIdx.x, lane = tid&31, wid = tid>>5;
    const int g = wid>>1, nb = (wid&1)*16;

    __shared__ __align__(16) __nv_bfloat16 sA[2][2][32][40];
    __shared__ __align__(16) __nv_bfloat16 sW[2][2][4][32][40];

    float C[2][2][4];
#pragma unroll
    for (int mh=0;mh<2;mh++)
#pragma unroll
        for (int f=0;f<2;f++)
#pragma unroll
            for (int r=0;r<4;r++) C[mh][f][r]=0.f;

    const __nv_bfloat16* Ah_[2] = {A1h + (long)a*a1zs, A2h + (long)a*BH};
    const __nv_bfloat16* Al_[2] = {A1l + (long)a*a1zs, A2l + (long)a*BH};
    const __nv_bfloat16* Wp[2][2] = {
        {W1h + (long)a*20*HH, W1l + (long)a*20*HH},
        {W2h + (long)a*20*HH, W2l + (long)a*20*HH}};

    const uint32_t sA_base = (uint32_t)__cvta_generic_to_shared(&sA[0][0][0][0]);
    const uint32_t sW_base = (uint32_t)__cvta_generic_to_shared(&sW[0][0][0][0][0]);

    const int a_row = lane&15, a_ko = (lane>>4)*8;
    const int b_r = lane&7, b_sel = lane>>3;
    const int b_rowoff = b_r + ((b_sel>>1)?8:0), b_ko = (b_sel&1)*8;

    auto prefetch = [&](int kc2){
        int st = kc2&1, s = kc2>>4, k0 = (kc2&15)*32;
        {   // A: hl = tid>>7, 256 x 16B
            int hl = tid>>7, lm = (tid>>2)&31, lq = tid&3;
            const __nv_bfloat16* src = (hl ? Al_[s] : Ah_[s]) + (long)(m0+lm)*512 + k0 + lq*8;
            cpa16(sA_base + (uint32_t)((((st*2+hl)*32 + lm)*40 + lq*8)*2), src);
        }
#pragma unroll
        for (int it=0; it<4; it++){   // W: 1024 x 16B
            int idx = tid + it*256;
            int q = idx&3, n = (idx>>2)&31, gg = (idx>>7)&3, hl = (idx>>9)&1;
            const __nv_bfloat16* src = Wp[s][hl] + (long)gg*HH + (long)(n0+n)*512 + k0 + q*8;
            cpa16(sW_base + (uint32_t)(((((st*2+hl)*4+gg)*32 + n)*40 + q*8)*2), src);
        }
        cpa_commit();
    };

    prefetch(0);
    for (int kc2=0; kc2<32; kc2++){
        const int st = kc2&1;
        if (kc2+1 < 32){
            prefetch(kc2+1);
            asm volatile("cp.async.wait_group 1;");
        } else {
            asm volatile("cp.async.wait_group 0;");
        }
        __syncthreads();
#pragma unroll
        for (int kf=0;kf<2;kf++){
            uint32_t ah[2][4], al[2][4];
#pragma unroll
            for (int mh=0;mh<2;mh++){
                uint32_t ad = sA_base + (uint32_t)(((((st*2+0)*32) + mh*16 + a_row)*40 + kf*16 + a_ko)*2);
                ldsm4(ad, ah[mh][0], ah[mh][1], ah[mh][2], ah[mh][3]);
                ad = sA_base + (uint32_t)(((((st*2+1)*32) + mh*16 + a_row)*40 + kf*16 + a_ko)*2);
                ldsm4(ad, al[mh][0], al[mh][1], al[mh][2], al[mh][3]);
            }
            uint32_t bh0,bh1,bh2,bh3, bl0,bl1,bl2,bl3;
            {
                uint32_t bd = sW_base + (uint32_t)((((((st*2+0)*4)+g)*32 + nb + b_rowoff)*40 + kf*16 + b_ko)*2);
                ldsm4(bd, bh0,bh1,bh2,bh3);
                bd = sW_base + (uint32_t)((((((st*2+1)*4)+g)*32 + nb + b_rowoff)*40 + kf*16 + b_ko)*2);
                ldsm4(bd, bl0,bl1,bl2,bl3);
            }
#pragma unroll
            for (int mh=0;mh<2;mh++){
                mma16816(C[mh][0], ah[mh], bh0, bh1);
                mma16816(C[mh][1], ah[mh], bh2, bh3);
                mma16816(C[mh][0], ah[mh], bl0, bl1);
                mma16816(C[mh][1], ah[mh], bl2, bl3);
                mma16816(C[mh][0], al[mh], bh0, bh1);
                mma16816(C[mh][1], al[mh], bh2, bh3);
            }
        }
        __syncthreads();
    }

    // epilogue: exchange gates via smem (reuse sW): preS[4][32][32] f32
    float* preS = (float*)&sW[0][0][0][0][0];
    {
        int r = lane>>2, i2 = (lane&3)*2;
#pragma unroll
        for (int mh=0;mh<2;mh++)
#pragma unroll
            for (int f=0;f<2;f++){
                int col = nb + f*8 + i2;
                preS[(g*32 + mh*16 + r)*32 + col]     = C[mh][f][0];
                preS[(g*32 + mh*16 + r)*32 + col+1]   = C[mh][f][1];
                preS[(g*32 + mh*16 + r+8)*32 + col]   = C[mh][f][2];
                preS[(g*32 + mh*16 + r+8)*32 + col+1] = C[mh][f][3];
            }
    }
    __syncthreads();
    {
        const float* cp = cpb + (long)a*BH;
        for (int cell = tid; cell < 1024; cell += 256){
            int m = cell>>5, n = cell&31;
            int gn = n0 + n;
            float p[4];
#pragma unroll
            for (int gg=0;gg<4;gg++)
                p[gg] = preS[(gg*32+m)*32 + n] + bl[((long)(a*5+l)*4+gg)*512 + gn];
            long o = (long)a*BH + (long)(m0+m)*512 + gn;
            float cn = sigf(p[1])*cp[(long)(m0+m)*512+gn] + sigf(p[0])*tanhf(p[2]);
            float hv = sigf(p[3])*tanhf(cn);
            cqb[o] = cn;
            __nv_bfloat16 hh = __float2bfloat16(hv);
            hbhq[o] = hh;
            hblq[o] = __float2bfloat16(hv - __bfloat162float(hh));
        }
    }
}

// ---- cell block: pipelined split-bf16 3-gate mma + fused cell_gate epilogue --
// grid (16 n-tiles[32/gate], 4 m-tiles[32], 15 (l,a)) = 960 blocks, 192 thr.
__global__ __launch_bounds__(192) void cell_mma(
    const __nv_bfloat16* __restrict__ Hgh, const __nv_bfloat16* __restrict__ Hgl,
    const __nv_bfloat16* __restrict__ Hbh, const __nv_bfloat16* __restrict__ Hbl,
    const __nv_bfloat16* __restrict__ Ghh, const __nv_bfloat16* __restrict__ Ghl,
    const __nv_bfloat16* __restrict__ Gph, const __nv_bfloat16* __restrict__ Gpl,
    const float* __restrict__ bg, const float* __restrict__ scb,
    float* __restrict__ icb, float* __restrict__ ccb)
{
    const int zb = blockIdx.z;
    const int m0 = blockIdx.y*32, n0 = blockIdx.x*32;
    const int tid = threadIdx.x, lane = tid&31, wid = tid>>5;
    const int g = wid>>1, nb = (wid&1)*16;

    __shared__ __align__(16) __nv_bfloat16 sA[2][2][32][40];
    __shared__ __align__(16) __nv_bfloat16 sW[2][2][3][32][40];

    float C[2][2][4];
#pragma unroll
    for (int mh=0;mh<2;mh++)
#pragma unroll
        for (int f=0;f<2;f++)
#pragma unroll
            for (int r=0;r<4;r++) C[mh][f][r]=0.f;

    const __nv_bfloat16* Ah_[2] = {Hgh, Hbh + (long)zb*BH};
    const __nv_bfloat16* Al_[2] = {Hgl, Hbl + (long)zb*BH};
    const __nv_bfloat16* Wp[2][2] = {
        {Ghh + (long)zb*3*HH, Ghl + (long)zb*3*HH},
        {Gph + (long)zb*3*HH, Gpl + (long)zb*3*HH}};

    const uint32_t sA_base = (uint32_t)__cvta_generic_to_shared(&sA[0][0][0][0]);
    const uint32_t sW_base = (uint32_t)__cvta_generic_to_shared(&sW[0][0][0][0][0]);

    const int a_row = lane&15, a_ko = (lane>>4)*8;
    const int b_r = lane&7, b_sel = lane>>3;
    const int b_rowoff = b_r + ((b_sel>>1)?8:0), b_ko = (b_sel&1)*8;

    auto prefetch = [&](int kc2){
        int st = kc2&1, s = kc2>>4, k0 = (kc2&15)*32;
#pragma unroll
        for (int it=0; it<2; it++){   // A: 256 x 16B over 192 thr
            int idx = tid + it*192;
            if (idx < 256){
                int hl = idx>>7, lm = (idx>>2)&31, lq = idx&3;
                const __nv_bfloat16* src = (hl ? Al_[s] : Ah_[s]) + (long)(m0+lm)*512 + k0 + lq*8;
                cpa16(sA_base + (uint32_t)((((st*2+hl)*32 + lm)*40 + lq*8)*2), src);
            }
        }
#pragma unroll
        for (int it=0; it<4; it++){   // W: 768 x 16B over 192 thr
            int idx = tid + it*192;
            int q = idx&3, n = (idx>>2)&31, rest = idx>>7;   // 0..5
            int gg = rest % 3, hl = rest / 3;
            const __nv_bfloat16* src = Wp[s][hl] + (long)gg*HH + (long)(n0+n)*512 + k0 + q*8;
            cpa16(sW_base + (uint32_t)(((((st*2+hl)*3+gg)*32 + n)*40 + q*8)*2), src);
        }
        cpa_commit();
    };

    prefetch(0);
    for (int kc2=0; kc2<32; kc2++){
        const int st = kc2&1;
        if (kc2+1 < 32){
            prefetch(kc2+1);
            asm volatile("cp.async.wait_group 1;");
        } else {
            asm volatile("cp.async.wait_group 0;");
        }
        __syncthreads();
#pragma unroll
        for (int kf=0;kf<2;kf++){
            uint32_t ah[2][4], al[2][4];
#pragma unroll
            for (int mh=0;mh<2;mh++){
                uint32_t ad = sA_base + (uint32_t)(((((st*2+0)*32) + mh*16 + a_row)*40 + kf*16 + a_ko)*2);
                ldsm4(ad, ah[mh][0], ah[mh][1], ah[mh][2], ah[mh][3]);
                ad = sA_base + (uint32_t)(((((st*2+1)*32) + mh*16 + a_row)*40 + kf*16 + a_ko)*2);
                ldsm4(ad, al[mh][0], al[mh][1], al[mh][2], al[mh][3]);
            }
            uint32_t bh0,bh1,bh2,bh3, bl0,bl1,bl2,bl3;
            {
                uint32_t bd = sW_base + (uint32_t)((((((st*2+0)*3)+g)*32 + nb + b_rowoff)*40 + kf*16 + b_ko)*2);
                ldsm4(bd, bh0,bh1,bh2,bh3);
                bd = sW_base + (uint32_t)((((((st*2+1)*3)+g)*32 + nb + b_rowoff)*40 + kf*16 + b_ko)*2);
                ldsm4(bd, bl0,bl1,bl2,bl3);
            }
#pragma unroll
            for (int mh=0;mh<2;mh++){
                mma16816(C[mh][0], ah[mh], bh0, bh1);
                mma16816(C[mh][1], ah[mh], bh2, bh3);
                mma16816(C[mh][0], ah[mh], bl0, bl1);
                mma16816(C[mh][1], ah[mh], bl2, bl3);
                mma16816(C[mh][0], al[mh], bh0, bh1);
                mma16816(C[mh][1], al[mh], bh2, bh3);
            }
        }
        __syncthreads();
    }

    float* preS = (float*)&sW[0][0][0][0][0];
    {
        int r = lane>>2, i2 = (lane&3)*2;
#pragma unroll
        for (int mh=0;mh<2;mh++)
#pragma unroll
            for (int f=0;f<2;f++){
                int col = nb + f*8 + i2;
                preS[(g*32 + mh*16 + r)*32 + col]     = C[mh][f][0];
                preS[(g*32 + mh*16 + r)*32 + col+1]   = C[mh][f][1];
                preS[(g*32 + mh*16 + r+8)*32 + col]   = C[mh][f][2];
                preS[(g*32 + mh*16 + r+8)*32 + col+1] = C[mh][f][3];
            }
    }
    __syncthreads();
    {
        const float* sc = scb + (long)zb*BH;
        for (int cell = tid; cell < 1024; cell += 192){
            int m = cell>>5, n = cell&31;
            int gn = n0 + n;
            float p[3];
#pragma unroll
            for (int gg=0;gg<3;gg++)
                p[gg] = preS[(gg*32+m)*32 + n] + bg[((long)zb*3+gg)*512 + gn];
            long r = (long)(m0+m)*512 + gn;
            float icv = sigf(p[0]) * sc[r];
            icb[(long)zb*BH + r] = icv;
            ccb[(long)zb*BH + r] = sigf(p[1])*tanhf(p[2]) + icv;
        }
    }
}

// ---- 64x64 NN GEMM for t12 (fp32) --------------------------------------------
__global__ __launch_bounds__(64) void gnn64(
    const float* __restrict__ icb, const float* __restrict__ ccb,
    const float* __restrict__ Wilc, float* __restrict__ Cb)
{
    const int zb = blockIdx.z;
    const int a = zb % 3, lw = zb / 3;
    const int w = lw & 1, l = lw >> 1;
    const float* A = (w ? ccb : icb) + (long)(l*3+a)*BH;
    const float* W = Wilc + (long)(l*3+a)*HH;
    float* C = Cb + (long)zb*BH;
    const int m0 = blockIdx.y*64, n0 = blockIdx.x*64;

    __shared__ __align__(16) float As[16][68], Ws[16][68];
    const int tid = threadIdx.x, tx = tid&7, ty = tid>>3;
    float acc[8][8];
#pragma unroll
    for (int i=0;i<8;i++)
#pragma unroll
        for (int j=0;j<8;j++) acc[i][j]=0.f;

    const int r0 = tid>>2;
    const int kq = (tid&3)<<2;

    for (int k0=0;k0<512;k0+=16){
#pragma unroll
        for (int i=0;i<4;i++){
            int row = r0 + 16*i;
            float4 v = *(const float4*)(A + (long)(m0+row)*512 + k0+kq);
            As[kq][row]=v.x; As[kq+1][row]=v.y; As[kq+2][row]=v.z; As[kq+3][row]=v.w;
            int j = tid + 64*i;
            int krow = j >> 4, nq = (j & 15) << 2;
            *(float4*)&Ws[krow][nq] = *(const float4*)(W + (long)(k0+krow)*512 + n0+nq);
        }
        __syncthreads();
#pragma unroll
        for (int kk=0;kk<16;kk++){
            float4 a0 = *(const float4*)&As[kk][ty*8];
            float4 a1 = *(const float4*)&As[kk][ty*8+4];
            float4 w0 = *(const float4*)&Ws[kk][tx*8];
            float4 w1 = *(const float4*)&Ws[kk][tx*8+4];
            float am[8] = {a0.x,a0.y,a0.z,a0.w,a1.x,a1.y,a1.z,a1.w};
            float wn[8] = {w0.x,w0.y,w0.z,w0.w,w1.x,w1.y,w1.z,w1.w};
#pragma unroll
            for (int i=0;i<8;i++)
#pragma unroll
                for (int j=0;j<8;j++) acc[i][j] += am[i]*wn[j];
        }
        __syncthreads();
    }
#pragma unroll
    for (int i=0;i<8;i++){
        float4 o0 = {acc[i][0],acc[i][1],acc[i][2],acc[i][3]};
        float4 o1 = {acc[i][4],acc[i][5],acc[i][6],acc[i][7]};
        float* cr = C + (long)(m0+ty*8+i)*512 + n0+tx*8;
        *(float4*)cr = o0;
        *(float4*)(cr+4) = o1;
    }
}

// ---- fused comb + single_li per-level partial GEMM (fp32) --------------------
__global__ __launch_bounds__(128) void combsl(
    const float* __restrict__ tp, const float* __restrict__ bilc,
    const float* __restrict__ Wsl, float* __restrict__ part)
{
    const int l = blockIdx.z, m0 = blockIdx.y*16, n0 = blockIdx.x*64;
    __shared__ __align__(16) float s1[16][520];
    __shared__ __align__(16) float Ws[16][68];
    const int tid = threadIdx.x;
    const int row = tid>>3, ln = tid&7;
    const int b = m0 + row;

    float mx = -1e30f;
    for (int i=0;i<64;i++){
        int z = ln + i*8;
        float v1 = bilc[(long)(l*3+0)*512+z] + bilc[(long)(l*3+1)*512+z] + bilc[(long)(l*3+2)*512+z];
#pragma unroll
        for (int a=0;a<3;a++)
            v1 += tp[((long)((2*l+0)*3+a))*BH + (long)b*512 + z];
        s1[row][z] = v1;
        mx = fmaxf(mx, v1);
    }
#pragma unroll
    for (int o=4;o>0;o>>=1) mx = fmaxf(mx, __shfl_xor_sync(0xffffffffu, mx, o, 8));
    float sm = 0.f;
    for (int i=0;i<64;i++){
        int z = ln + i*8;
        float e = expf(s1[row][z] - mx);
        s1[row][z] = e; sm += e;
    }
#pragma unroll
    for (int o=4;o>0;o>>=1) sm += __shfl_xor_sync(0xffffffffu, sm, o, 8);
    float inv = 1.f/sm;
    for (int i=0;i<64;i++){
        int z = ln + i*8;
        float v2 = bilc[(long)(l*3+0)*512+z] + bilc[(long)(l*3+1)*512+z] + bilc[(long)(l*3+2)*512+z];
#pragma unroll
        for (int a=0;a<3;a++)
            v2 += tp[((long)((2*l+1)*3+a))*BH + (long)b*512 + z];
        s1[row][z] = s1[row][z] * inv * sigf(v2);
    }
    __syncthreads();

    const int tx = tid&15, ty = tid>>4;
    const int wlm = tid>>1, wlk = (tid&1)<<3;
    float acc[2][4];
#pragma unroll
    for (int i=0;i<2;i++)
#pragma unroll
        for (int j=0;j<4;j++) acc[i][j]=0.f;
    for (int k0=0;k0<512;k0+=16){
        const float* wp = Wsl + (long)(n0+wlm)*2560 + l*512 + k0+wlk;
        float4 u0=*(const float4*)wp, u1=*(const float4*)(wp+4);
        Ws[wlk][wlm]=u0.x; Ws[wlk+1][wlm]=u0.y; Ws[wlk+2][wlm]=u0.z; Ws[wlk+3][wlm]=u0.w;
        Ws[wlk+4][wlm]=u1.x; Ws[wlk+5][wlm]=u1.y; Ws[wlk+6][wlm]=u1.z; Ws[wlk+7][wlm]=u1.w;
        __syncthreads();
#pragma unroll
        for (int kk=0;kk<16;kk++){
            float a0 = s1[ty*2][k0+kk], a1 = s1[ty*2+1][k0+kk];
            float4 w = *(const float4*)&Ws[kk][tx*4];
            acc[0][0]+=a0*w.x; acc[0][1]+=a0*w.y; acc[0][2]+=a0*w.z; acc[0][3]+=a0*w.w;
            acc[1][0]+=a1*w.x; acc[1][1]+=a1*w.y; acc[1][2]+=a1*w.z; acc[1][3]+=a1*w.w;
        }
        __syncthreads();
    }
#pragma unroll
    for (int i=0;i<2;i++)
#pragma unroll
        for (int j=0;j<4;j++)
            part[(long)l*BH + (long)(m0+ty*2+i)*512 + n0+tx*4+j] = acc[i][j];
}

// ---- combine partials + bias -> h_g(bf16 split); per-step linear -> y --------
__global__ void y_kernel(const float* __restrict__ part, const float* __restrict__ bsl,
                         __nv_bfloat16* __restrict__ hgh, __nv_bfloat16* __restrict__ hgl,
                         const float* __restrict__ wlin_t,
                         const float* __restrict__ blin_t, float* __restrict__ outp)
{
    int b = blockIdx.x, tid = threadIdx.x;
    float s = 0.f;
    for (int j=tid; j<512; j+=128){
        long idx = (long)b*512 + j;
        float h = bsl[j] + part[idx] + part[BH+idx] + part[2L*BH+idx]
                + part[3L*BH+idx] + part[4L*BH+idx];
        __nv_bfloat16 hh = __float2bfloat16(h);
        hgh[idx] = hh;
        hgl[idx] = __float2bfloat16(h - __bfloat162float(hh));
        s += h * wlin_t[j];
    }
    __shared__ float red[128];
    red[tid]=s; __syncthreads();
    for (int st=64; st>0; st>>=1){ if (tid<st) red[tid]+=red[tid+st]; __syncthreads(); }
    if (tid==0) outp[b] = red[0] + blin_t[0];
}

extern "C" void kernel_launch(void* const* d_in, const int* in_sizes, int n_in,
                              void* d_out, int out_size)
{
    const float* x     = (const float*)d_in[0];
    const float* Wx    = (const float*)d_in[1];
    const float* Wh    = (const float*)d_in[2];
    const float* bl    = (const float*)d_in[3];
    const float* Wg_h  = (const float*)d_in[4];
    const float* Wg_p  = (const float*)d_in[5];
    const float* bg    = (const float*)d_in[6];
    const float* Wilc  = (const float*)d_in[7];
    const float* bilc  = (const float*)d_in[8];
    const float* Wsl   = (const float*)d_in[9];
    const float* bsl   = (const float*)d_in[10];
    const float* Wlin  = (const float*)d_in[11];
    const float* blin  = (const float*)d_in[12];
    float* out = (float*)d_out;

    float *c, *ic, *cc, *tp, *slp;
    __nv_bfloat16 *wxh, *wxl, *whh, *whl, *xh, *xl, *hbh, *hbl;
    __nv_bfloat16 *ghh, *ghl, *gph, *gpl, *hgh, *hgl;
    cudaGetSymbolAddress((void**)&c,   g_c);
    cudaGetSymbolAddress((void**)&ic,  g_ic);
    cudaGetSymbolAddress((void**)&cc,  g_cc);
    cudaGetSymbolAddress((void**)&tp,  g_tp);
    cudaGetSymbolAddress((void**)&slp, g_slp);
    cudaGetSymbolAddress((void**)&wxh, g_Wxhi);
    cudaGetSymbolAddress((void**)&wxl, g_Wxlo);
    cudaGetSymbolAddress((void**)&whh, g_Whhi);
    cudaGetSymbolAddress((void**)&whl, g_Whlo);
    cudaGetSymbolAddress((void**)&ghh, g_Wghh);
    cudaGetSymbolAddress((void**)&ghl, g_Wghl);
    cudaGetSymbolAddress((void**)&gph, g_Wgph);
    cudaGetSymbolAddress((void**)&gpl, g_Wgpl);
    cudaGetSymbolAddress((void**)&xh,  g_xh);
    cudaGetSymbolAddress((void**)&xl,  g_xl);
    cudaGetSymbolAddress((void**)&hbh, g_hbh);
    cudaGetSymbolAddress((void**)&hbl, g_hbl);
    cudaGetSymbolAddress((void**)&hgh, g_hgh);
    cudaGetSymbolAddress((void**)&hgl, g_hgl);

    conv_w_lstm<<<1024,256>>>(Wx, Wh, wxh, wxl, whh, whl);
    conv_wg<<<1024,256>>>(Wg_h, Wg_p, ghh, ghl, gph, gpl);
    conv_x<<<512,256>>>(x, xh, xl);
    zero_kernel<<<256,256>>>(c, hbh, hbl, hgh, hgl);

    for (int t=0; t<TT; t++){
        int p = t & 1, q = p ^ 1;
        const float* cp = c + (long)p*NLA*BH;
        float*       cq = c + (long)q*NLA*BH;
        const __nv_bfloat16* hbhp = hbh + (long)p*NLA*BH;
        __nv_bfloat16*       hbhq = hbh + (long)q*NLA*BH;
        const __nv_bfloat16* hblp = hbl + (long)p*NLA*BH;
        __nv_bfloat16*       hblq = hbl + (long)q*NLA*BH;
        const __nv_bfloat16* hghp = hgh + (long)p*BH;
        __nv_bfloat16*       hghq = hgh + (long)q*BH;
        const __nv_bfloat16* hglp = hgl + (long)p*BH;
        __nv_bfloat16*       hglq = hgl + (long)q*BH;

        for (int l=0; l<5; l++){
            const __nv_bfloat16 *A1h_, *A1l_;
            long a1zs;
            if (l==0){ A1h_ = xh + (long)t*BH; A1l_ = xl + (long)t*BH; a1zs = 0; }
            else { A1h_ = hbhq + (long)(l-1)*3*BH; A1l_ = hblq + (long)(l-1)*3*BH; a1zs = BH; }
            lstm_mma<<<dim3(16,4,3),256>>>(
                A1h_, A1l_, a1zs,
                hbhp + (long)l*3*BH, hblp + (long)l*3*BH,
                wxh + (long)l*4*HH, wxl + (long)l*4*HH,
                whh + (long)l*4*HH, whl + (long)l*4*HH,
                bl, l, cp + (long)l*3*BH,
                cq + (long)l*3*BH,
                hbhq + (long)l*3*BH, hblq + (long)l*3*BH);
        }
        cell_mma<<<dim3(16,4,15),192>>>(
            hghp, hglp, hbhq, hblq,
            ghh, ghl, gph, gpl,
            bg, cq, ic, cc);
        gnn64<<<dim3(8,2,30),64>>>(ic, cc, Wilc, tp);
        combsl<<<dim3(8,8,5),128>>>(tp, bilc, Wsl, slp);
        y_kernel<<<128,128>>>(slp, bsl, hghq, hglq, Wlin + (long)t*HD, blin + t, out + (long)t*BSZ);
    }
}

// round 9
// speedup vs baseline: 4.7749x; 1.0509x over previous
#include <cuda_runtime.h>
#include <cuda_bf16.h>
#include <math.h>
#include <stdint.h>

#define TT 64
#define BSZ 128
#define HD 512
#define NLA 15
#define BH (BSZ*HD)
#define HH (HD*HD)
#define NWL (3L*5*4*512*512)
#define NWG (5L*3*3*512*512)

__device__ float g_c[2][NLA][BH];
__device__ float g_tp[30][BH];
__device__ float g_slp[5][BH];

__device__ __nv_bfloat16 g_Wxhi[NWL], g_Wxlo[NWL], g_Whhi[NWL], g_Whlo[NWL];
__device__ __nv_bfloat16 g_Wghh[NWG], g_Wghl[NWG], g_Wgph[NWG], g_Wgpl[NWG];
__device__ __nv_bfloat16 g_Wthi[15L*HH], g_Wtlo[15L*HH];
__device__ __nv_bfloat16 g_xh[(long)TT*BH], g_xl[(long)TT*BH];
__device__ __nv_bfloat16 g_hbh[2][NLA][BH], g_hbl[2][NLA][BH];
__device__ __nv_bfloat16 g_hgh[2][BH], g_hgl[2][BH];
__device__ __nv_bfloat16 g_ichi[NLA][BH], g_iclo[NLA][BH];
__device__ __nv_bfloat16 g_cchi[NLA][BH], g_cclo[NLA][BH];

__device__ __forceinline__ float sigf(float x){ return 1.0f/(1.0f+expf(-x)); }

__global__ void zero_kernel(float* c0, __nv_bfloat16* hbh0, __nv_bfloat16* hbl0,
                            __nv_bfloat16* hgh0, __nv_bfloat16* hgl0){
    int n = NLA*BH;
    __nv_bfloat16 z = __float2bfloat16(0.f);
    for (int i = blockIdx.x*blockDim.x+threadIdx.x; i < n; i += gridDim.x*blockDim.x){
        c0[i]=0.f; hbh0[i]=z; hbl0[i]=z;
        if (i<BH){ hgh0[i]=z; hgl0[i]=z; }
    }
}

__global__ void conv_w_lstm(const float* __restrict__ Wx, const float* __restrict__ Wh,
    __nv_bfloat16* xh, __nv_bfloat16* xl, __nv_bfloat16* hh, __nv_bfloat16* hl){
    for (long i = (long)blockIdx.x*blockDim.x+threadIdx.x; i < NWL;
         i += (long)gridDim.x*blockDim.x){
        float w = Wx[i];
        __nv_bfloat16 hi = __float2bfloat16(w);
        xh[i] = hi; xl[i] = __float2bfloat16(w - __bfloat162float(hi));
        w = Wh[i];
        hi = __float2bfloat16(w);
        hh[i] = hi; hl[i] = __float2bfloat16(w - __bfloat162float(hi));
    }
}

__global__ void conv_wg(const float* __restrict__ Gh, const float* __restrict__ Gp,
    __nv_bfloat16* ghh, __nv_bfloat16* ghl, __nv_bfloat16* gph, __nv_bfloat16* gpl){
    for (long i = (long)blockIdx.x*blockDim.x+threadIdx.x; i < NWG;
         i += (long)gridDim.x*blockDim.x){
        float w = Gh[i];
        __nv_bfloat16 hi = __float2bfloat16(w);
        ghh[i] = hi; ghl[i] = __float2bfloat16(w - __bfloat162float(hi));
        w = Gp[i];
        hi = __float2bfloat16(w);
        gph[i] = hi; gpl[i] = __float2bfloat16(w - __bfloat162float(hi));
    }
}

// transpose Wilc[l,a][z][y] -> Wt[l,a][y][z], split to bf16 hi/lo
__global__ void conv_wilc(const float* __restrict__ W,
                          __nv_bfloat16* th, __nv_bfloat16* tl){
    int zb = blockIdx.z;
    int z0 = blockIdx.y*32, y0 = blockIdx.x*32;
    __shared__ float s[32][33];
    int tx = threadIdx.x&31, ty = threadIdx.x>>5;
    const float* Wb = W + (long)zb*HH;
#pragma unroll
    for (int r=0;r<4;r++)
        s[ty+r*8][tx] = Wb[(long)(z0+ty+r*8)*512 + y0+tx];
    __syncthreads();
#pragma unroll
    for (int r=0;r<4;r++){
        float w = s[tx][ty+r*8];
        __nv_bfloat16 hi = __float2bfloat16(w);
        long o = (long)zb*HH + (long)(y0+ty+r*8)*512 + z0+tx;
        th[o]=hi; tl[o]=__float2bfloat16(w - __bfloat162float(hi));
    }
}

__global__ void conv_x(const float* __restrict__ x, __nv_bfloat16* xh, __nv_bfloat16* xl){
    const long N = (long)TT*BH;
    for (long i = (long)blockIdx.x*blockDim.x+threadIdx.x; i < N;
         i += (long)gridDim.x*blockDim.x){
        float w = x[i];
        __nv_bfloat16 hi = __float2bfloat16(w);
        xh[i] = hi; xl[i] = __float2bfloat16(w - __bfloat162float(hi));
    }
}

__device__ __forceinline__ void ldsm4(uint32_t addr, uint32_t &r0, uint32_t &r1,
                                      uint32_t &r2, uint32_t &r3){
    asm volatile("ldmatrix.sync.aligned.m8n8.x4.shared.b16 {%0,%1,%2,%3}, [%4];"
        : "=r"(r0),"=r"(r1),"=r"(r2),"=r"(r3) : "r"(addr));
}
__device__ __forceinline__ void mma16816(float* c, const uint32_t* a,
                                         uint32_t b0, uint32_t b1){
    asm volatile("mma.sync.aligned.m16n8k16.row.col.f32.bf16.bf16.f32 "
        "{%0,%1,%2,%3},{%4,%5,%6,%7},{%8,%9},{%0,%1,%2,%3};"
        : "+f"(c[0]),"+f"(c[1]),"+f"(c[2]),"+f"(c[3])
        : "r"(a[0]),"r"(a[1]),"r"(a[2]),"r"(a[3]),"r"(b0),"r"(b1));
}
__device__ __forceinline__ void cpa16(uint32_t dst, const void* src){
    asm volatile("cp.async.ca.shared.global [%0], [%1], 16;" :: "r"(dst), "l"(src));
}
__device__ __forceinline__ void cpa_commit(){ asm volatile("cp.async.commit_group;"); }

// ---- LSTM level: pipelined split-bf16 mma + fused gate epilogue --------------
__global__ __launch_bounds__(256) void lstm_mma(
    const __nv_bfloat16* __restrict__ A1h, const __nv_bfloat16* __restrict__ A1l, long a1zs,
    const __nv_bfloat16* __restrict__ A2h, const __nv_bfloat16* __restrict__ A2l,
    const __nv_bfloat16* __restrict__ W1h, const __nv_bfloat16* __restrict__ W1l,
    const __nv_bfloat16* __restrict__ W2h, const __nv_bfloat16* __restrict__ W2l,
    const float* __restrict__ bl, int l, const float* __restrict__ cpb,
    float* __restrict__ cqb,
    __nv_bfloat16* __restrict__ hbhq, __nv_bfloat16* __restrict__ hblq)
{
    const int a = blockIdx.z;
    const int m0 = blockIdx.y*32, n0 = blockIdx.x*32;
    const int tid = threadIdx.x, lane = tid&31, wid = tid>>5;
    const int g = wid>>1, nb = (wid&1)*16;

    __shared__ __align__(16) __nv_bfloat16 sA[2][2][32][40];
    __shared__ __align__(16) __nv_bfloat16 sW[2][2][4][32][40];

    float C[2][2][4];
#pragma unroll
    for (int mh=0;mh<2;mh++)
#pragma unroll
        for (int f=0;f<2;f++)
#pragma unroll
            for (int r=0;r<4;r++) C[mh][f][r]=0.f;

    const __nv_bfloat16* Ah_[2] = {A1h + (long)a*a1zs, A2h + (long)a*BH};
    const __nv_bfloat16* Al_[2] = {A1l + (long)a*a1zs, A2l + (long)a*BH};
    const __nv_bfloat16* Wp[2][2] = {
        {W1h + (long)a*20*HH, W1l + (long)a*20*HH},
        {W2h + (long)a*20*HH, W2l + (long)a*20*HH}};

    const uint32_t sA_base = (uint32_t)__cvta_generic_to_shared(&sA[0][0][0][0]);
    const uint32_t sW_base = (uint32_t)__cvta_generic_to_shared(&sW[0][0][0][0][0]);

    const int a_row = lane&15, a_ko = (lane>>4)*8;
    const int b_r = lane&7, b_sel = lane>>3;
    const int b_rowoff = b_r + ((b_sel>>1)?8:0), b_ko = (b_sel&1)*8;

    auto prefetch = [&](int kc2){
        int st = kc2&1, s = kc2>>4, k0 = (kc2&15)*32;
        {
            int hl = tid>>7, lm = (tid>>2)&31, lq = tid&3;
            const __nv_bfloat16* src = (hl ? Al_[s] : Ah_[s]) + (long)(m0+lm)*512 + k0 + lq*8;
            cpa16(sA_base + (uint32_t)((((st*2+hl)*32 + lm)*40 + lq*8)*2), src);
        }
#pragma unroll
        for (int it=0; it<4; it++){
            int idx = tid + it*256;
            int q = idx&3, n = (idx>>2)&31, gg = (idx>>7)&3, hl = (idx>>9)&1;
            const __nv_bfloat16* src = Wp[s][hl] + (long)gg*HH + (long)(n0+n)*512 + k0 + q*8;
            cpa16(sW_base + (uint32_t)(((((st*2+hl)*4+gg)*32 + n)*40 + q*8)*2), src);
        }
        cpa_commit();
    };

    prefetch(0);
    for (int kc2=0; kc2<32; kc2++){
        const int st = kc2&1;
        if (kc2+1 < 32){
            prefetch(kc2+1);
            asm volatile("cp.async.wait_group 1;");
        } else {
            asm volatile("cp.async.wait_group 0;");
        }
        __syncthreads();
#pragma unroll
        for (int kf=0;kf<2;kf++){
            uint32_t ah[2][4], al[2][4];
#pragma unroll
            for (int mh=0;mh<2;mh++){
                uint32_t ad = sA_base + (uint32_t)(((((st*2+0)*32) + mh*16 + a_row)*40 + kf*16 + a_ko)*2);
                ldsm4(ad, ah[mh][0], ah[mh][1], ah[mh][2], ah[mh][3]);
                ad = sA_base + (uint32_t)(((((st*2+1)*32) + mh*16 + a_row)*40 + kf*16 + a_ko)*2);
                ldsm4(ad, al[mh][0], al[mh][1], al[mh][2], al[mh][3]);
            }
            uint32_t bh0,bh1,bh2,bh3, bl0,bl1,bl2,bl3;
            {
                uint32_t bd = sW_base + (uint32_t)((((((st*2+0)*4)+g)*32 + nb + b_rowoff)*40 + kf*16 + b_ko)*2);
                ldsm4(bd, bh0,bh1,bh2,bh3);
                bd = sW_base + (uint32_t)((((((st*2+1)*4)+g)*32 + nb + b_rowoff)*40 + kf*16 + b_ko)*2);
                ldsm4(bd, bl0,bl1,bl2,bl3);
            }
#pragma unroll
            for (int mh=0;mh<2;mh++){
                mma16816(C[mh][0], ah[mh], bh0, bh1);
                mma16816(C[mh][1], ah[mh], bh2, bh3);
                mma16816(C[mh][0], ah[mh], bl0, bl1);
                mma16816(C[mh][1], ah[mh], bl2, bl3);
                mma16816(C[mh][0], al[mh], bh0, bh1);
                mma16816(C[mh][1], al[mh], bh2, bh3);
            }
        }
        __syncthreads();
    }

    float* preS = (float*)&sW[0][0][0][0][0];
    {
        int r = lane>>2, i2 = (lane&3)*2;
#pragma unroll
        for (int mh=0;mh<2;mh++)
#pragma unroll
            for (int f=0;f<2;f++){
                int col = nb + f*8 + i2;
                preS[(g*32 + mh*16 + r)*32 + col]     = C[mh][f][0];
                preS[(g*32 + mh*16 + r)*32 + col+1]   = C[mh][f][1];
                preS[(g*32 + mh*16 + r+8)*32 + col]   = C[mh][f][2];
                preS[(g*32 + mh*16 + r+8)*32 + col+1] = C[mh][f][3];
            }
    }
    __syncthreads();
    {
        const float* cp = cpb + (long)a*BH;
        for (int cell = tid; cell < 1024; cell += 256){
            int m = cell>>5, n = cell&31;
            int gn = n0 + n;
            float p[4];
#pragma unroll
            for (int gg=0;gg<4;gg++)
                p[gg] = preS[(gg*32+m)*32 + n] + bl[((long)(a*5+l)*4+gg)*512 + gn];
            long o = (long)a*BH + (long)(m0+m)*512 + gn;
            float cn = sigf(p[1])*cp[(long)(m0+m)*512+gn] + sigf(p[0])*tanhf(p[2]);
            float hv = sigf(p[3])*tanhf(cn);
            cqb[o] = cn;
            __nv_bfloat16 hh = __float2bfloat16(hv);
            hbhq[o] = hh;
            hblq[o] = __float2bfloat16(hv - __bfloat162float(hh));
        }
    }
}

// ---- cell block: split-bf16 3-gate mma + epilogue emitting bf16 ic/cc splits -
__global__ __launch_bounds__(192) void cell_mma(
    const __nv_bfloat16* __restrict__ Hgh, const __nv_bfloat16* __restrict__ Hgl,
    const __nv_bfloat16* __restrict__ Hbh, const __nv_bfloat16* __restrict__ Hbl,
    const __nv_bfloat16* __restrict__ Ghh, const __nv_bfloat16* __restrict__ Ghl,
    const __nv_bfloat16* __restrict__ Gph, const __nv_bfloat16* __restrict__ Gpl,
    const float* __restrict__ bg, const float* __restrict__ scb,
    __nv_bfloat16* __restrict__ ichi, __nv_bfloat16* __restrict__ iclo,
    __nv_bfloat16* __restrict__ cchi, __nv_bfloat16* __restrict__ cclo)
{
    const int zb = blockIdx.z;
    const int m0 = blockIdx.y*32, n0 = blockIdx.x*32;
    const int tid = threadIdx.x, lane = tid&31, wid = tid>>5;
    const int g = wid>>1, nb = (wid&1)*16;

    __shared__ __align__(16) __nv_bfloat16 sA[2][2][32][40];
    __shared__ __align__(16) __nv_bfloat16 sW[2][2][3][32][40];

    float C[2][2][4];
#pragma unroll
    for (int mh=0;mh<2;mh++)
#pragma unroll
        for (int f=0;f<2;f++)
#pragma unroll
            for (int r=0;r<4;r++) C[mh][f][r]=0.f;

    const __nv_bfloat16* Ah_[2] = {Hgh, Hbh + (long)zb*BH};
    const __nv_bfloat16* Al_[2] = {Hgl, Hbl + (long)zb*BH};
    const __nv_bfloat16* Wp[2][2] = {
        {Ghh + (long)zb*3*HH, Ghl + (long)zb*3*HH},
        {Gph + (long)zb*3*HH, Gpl + (long)zb*3*HH}};

    const uint32_t sA_base = (uint32_t)__cvta_generic_to_shared(&sA[0][0][0][0]);
    const uint32_t sW_base = (uint32_t)__cvta_generic_to_shared(&sW[0][0][0][0][0]);

    const int a_row = lane&15, a_ko = (lane>>4)*8;
    const int b_r = lane&7, b_sel = lane>>3;
    const int b_rowoff = b_r + ((b_sel>>1)?8:0), b_ko = (b_sel&1)*8;

    auto prefetch = [&](int kc2){
        int st = kc2&1, s = kc2>>4, k0 = (kc2&15)*32;
#pragma unroll
        for (int it=0; it<2; it++){
            int idx = tid + it*192;
            if (idx < 256){
                int hl = idx>>7, lm = (idx>>2)&31, lq = idx&3;
                const __nv_bfloat16* src = (hl ? Al_[s] : Ah_[s]) + (long)(m0+lm)*512 + k0 + lq*8;
                cpa16(sA_base + (uint32_t)((((st*2+hl)*32 + lm)*40 + lq*8)*2), src);
            }
        }
#pragma unroll
        for (int it=0; it<4; it++){
            int idx = tid + it*192;
            int q = idx&3, n = (idx>>2)&31, rest = idx>>7;
            int gg = rest % 3, hl = rest / 3;
            const __nv_bfloat16* src = Wp[s][hl] + (long)gg*HH + (long)(n0+n)*512 + k0 + q*8;
            cpa16(sW_base + (uint32_t)(((((st*2+hl)*3+gg)*32 + n)*40 + q*8)*2), src);
        }
        cpa_commit();
    };

    prefetch(0);
    for (int kc2=0; kc2<32; kc2++){
        const int st = kc2&1;
        if (kc2+1 < 32){
            prefetch(kc2+1);
            asm volatile("cp.async.wait_group 1;");
        } else {
            asm volatile("cp.async.wait_group 0;");
        }
        __syncthreads();
#pragma unroll
        for (int kf=0;kf<2;kf++){
            uint32_t ah[2][4], al[2][4];
#pragma unroll
            for (int mh=0;mh<2;mh++){
                uint32_t ad = sA_base + (uint32_t)(((((st*2+0)*32) + mh*16 + a_row)*40 + kf*16 + a_ko)*2);
                ldsm4(ad, ah[mh][0], ah[mh][1], ah[mh][2], ah[mh][3]);
                ad = sA_base + (uint32_t)(((((st*2+1)*32) + mh*16 + a_row)*40 + kf*16 + a_ko)*2);
                ldsm4(ad, al[mh][0], al[mh][1], al[mh][2], al[mh][3]);
            }
            uint32_t bh0,bh1,bh2,bh3, bl0,bl1,bl2,bl3;
            {
                uint32_t bd = sW_base + (uint32_t)((((((st*2+0)*3)+g)*32 + nb + b_rowoff)*40 + kf*16 + b_ko)*2);
                ldsm4(bd, bh0,bh1,bh2,bh3);
                bd = sW_base + (uint32_t)((((((st*2+1)*3)+g)*32 + nb + b_rowoff)*40 + kf*16 + b_ko)*2);
                ldsm4(bd, bl0,bl1,bl2,bl3);
            }
#pragma unroll
            for (int mh=0;mh<2;mh++){
                mma16816(C[mh][0], ah[mh], bh0, bh1);
                mma16816(C[mh][1], ah[mh], bh2, bh3);
                mma16816(C[mh][0], ah[mh], bl0, bl1);
                mma16816(C[mh][1], ah[mh], bl2, bl3);
                mma16816(C[mh][0], al[mh], bh0, bh1);
                mma16816(C[mh][1], al[mh], bh2, bh3);
            }
        }
        __syncthreads();
    }

    float* preS = (float*)&sW[0][0][0][0][0];
    {
        int r = lane>>2, i2 = (lane&3)*2;
#pragma unroll
        for (int mh=0;mh<2;mh++)
#pragma unroll
            for (int f=0;f<2;f++){
                int col = nb + f*8 + i2;
                preS[(g*32 + mh*16 + r)*32 + col]     = C[mh][f][0];
                preS[(g*32 + mh*16 + r)*32 + col+1]   = C[mh][f][1];
                preS[(g*32 + mh*16 + r+8)*32 + col]   = C[mh][f][2];
                preS[(g*32 + mh*16 + r+8)*32 + col+1] = C[mh][f][3];
            }
    }
    __syncthreads();
    {
        const float* sc = scb + (long)zb*BH;
        for (int cell = tid; cell < 1024; cell += 192){
            int m = cell>>5, n = cell&31;
            int gn = n0 + n;
            float p[3];
#pragma unroll
            for (int gg=0;gg<3;gg++)
                p[gg] = preS[(gg*32+m)*32 + n] + bg[((long)zb*3+gg)*512 + gn];
            long r = (long)(m0+m)*512 + gn;
            float icv = sigf(p[0]) * sc[r];
            float ccv = sigf(p[1])*tanhf(p[2]) + icv;
            long o = (long)zb*BH + r;
            __nv_bfloat16 ih = __float2bfloat16(icv);
            ichi[o] = ih; iclo[o] = __float2bfloat16(icv - __bfloat162float(ih));
            __nv_bfloat16 ch = __float2bfloat16(ccv);
            cchi[o] = ch; cclo[o] = __float2bfloat16(ccv - __bfloat162float(ch));
        }
    }
}

// ---- t12: dual-stream split-bf16 mma vs shared Wt tile -----------------------
// grid (16 n-tiles[32], 4 m-tiles[32], 15 (l,a)), 128 thr (4 warps).
// warp w: stream s = w>>1 (0=ic->t1, 1=cc->t2), nb = (w&1)*16.
__global__ __launch_bounds__(128) void t12_mma(
    const __nv_bfloat16* __restrict__ ichi, const __nv_bfloat16* __restrict__ iclo,
    const __nv_bfloat16* __restrict__ cchi, const __nv_bfloat16* __restrict__ cclo,
    const __nv_bfloat16* __restrict__ Wth, const __nv_bfloat16* __restrict__ Wtl,
    float* __restrict__ tp)
{
    const int zb = blockIdx.z;
    const int l = zb/3, a = zb%3;
    const int m0 = blockIdx.y*32, n0 = blockIdx.x*32;
    const int tid = threadIdx.x, lane = tid&31, wid = tid>>5;
    const int s = wid>>1, nb = (wid&1)*16;

    __shared__ __align__(16) __nv_bfloat16 sA[2][2][2][32][40];  // st, stream, hl
    __shared__ __align__(16) __nv_bfloat16 sW[2][2][32][40];     // st, hl

    float C[2][2][4];
#pragma unroll
    for (int mh=0;mh<2;mh++)
#pragma unroll
        for (int f=0;f<2;f++)
#pragma unroll
            for (int r=0;r<4;r++) C[mh][f][r]=0.f;

    const __nv_bfloat16* Asrc[2][2] = {
        {ichi + (long)zb*BH, iclo + (long)zb*BH},
        {cchi + (long)zb*BH, cclo + (long)zb*BH}};
    const __nv_bfloat16* Wsrc[2] = {Wth + (long)zb*HH, Wtl + (long)zb*HH};

    const uint32_t sA_base = (uint32_t)__cvta_generic_to_shared(&sA[0][0][0][0][0]);
    const uint32_t sW_base = (uint32_t)__cvta_generic_to_shared(&sW[0][0][0][0]);

    const int a_row = lane&15, a_ko = (lane>>4)*8;
    const int b_r = lane&7, b_sel = lane>>3;
    const int b_rowoff = b_r + ((b_sel>>1)?8:0), b_ko = (b_sel&1)*8;

    auto prefetch = [&](int kc){
        int st = kc&1, k0 = kc*32;
#pragma unroll
        for (int it=0; it<4; it++){   // A: 512 x 16B over 128 thr
            int idx = tid + it*128;
            int q = idx&3, row = (idx>>2)&31, hl = (idx>>7)&1, ss = (idx>>8)&1;
            const __nv_bfloat16* src = Asrc[ss][hl] + (long)(m0+row)*512 + k0 + q*8;
            cpa16(sA_base + (uint32_t)(((((st*2+ss)*2+hl)*32 + row)*40 + q*8)*2), src);
        }
#pragma unroll
        for (int it=0; it<2; it++){   // W: 256 x 16B
            int idx = tid + it*128;
            int q = idx&3, row = (idx>>2)&31, hl = (idx>>7)&1;
            const __nv_bfloat16* src = Wsrc[hl] + (long)(n0+row)*512 + k0 + q*8;
            cpa16(sW_base + (uint32_t)((((st*2+hl)*32 + row)*40 + q*8)*2), src);
        }
        cpa_commit();
    };

    prefetch(0);
    for (int kc=0; kc<16; kc++){
        const int st = kc&1;
        if (kc+1 < 16){
            prefetch(kc+1);
            asm volatile("cp.async.wait_group 1;");
        } else {
            asm volatile("cp.async.wait_group 0;");
        }
        __syncthreads();
#pragma unroll
        for (int kf=0;kf<2;kf++){
            uint32_t ah[2][4], al[2][4];
#pragma unroll
            for (int mh=0;mh<2;mh++){
                uint32_t ad = sA_base + (uint32_t)((((((st*2+s)*2+0)*32) + mh*16 + a_row)*40 + kf*16 + a_ko)*2);
                ldsm4(ad, ah[mh][0], ah[mh][1], ah[mh][2], ah[mh][3]);
                ad = sA_base + (uint32_t)((((((st*2+s)*2+1)*32) + mh*16 + a_row)*40 + kf*16 + a_ko)*2);
                ldsm4(ad, al[mh][0], al[mh][1], al[mh][2], al[mh][3]);
            }
            uint32_t bh0,bh1,bh2,bh3, bl0,bl1,bl2,bl3;
            {
                uint32_t bd = sW_base + (uint32_t)((((st*2+0)*32 + nb + b_rowoff)*40 + kf*16 + b_ko)*2);
                ldsm4(bd, bh0,bh1,bh2,bh3);
                bd = sW_base + (uint32_t)((((st*2+1)*32 + nb + b_rowoff)*40 + kf*16 + b_ko)*2);
                ldsm4(bd, bl0,bl1,bl2,bl3);
            }
#pragma unroll
            for (int mh=0;mh<2;mh++){
                mma16816(C[mh][0], ah[mh], bh0, bh1);
                mma16816(C[mh][1], ah[mh], bh2, bh3);
                mma16816(C[mh][0], ah[mh], bl0, bl1);
                mma16816(C[mh][1], ah[mh], bl2, bl3);
                mma16816(C[mh][0], al[mh], bh0, bh1);
                mma16816(C[mh][1], al[mh], bh2, bh3);
            }
        }
        __syncthreads();
    }

    // write C to tp[(2l+s)*3+a]
    float* tpo = tp + ((long)((2*l+s)*3+a))*BH;
    {
        int r = lane>>2, i2 = (lane&3)*2;
#pragma unroll
        for (int mh=0;mh<2;mh++)
#pragma unroll
            for (int f=0;f<2;f++){
                int row = m0 + mh*16 + r;
                int col = n0 + nb + f*8 + i2;
                tpo[(long)row*512 + col]       = C[mh][f][0];
                tpo[(long)row*512 + col+1]     = C[mh][f][1];
                tpo[(long)(row+8)*512 + col]   = C[mh][f][2];
                tpo[(long)(row+8)*512 + col+1] = C[mh][f][3];
            }
    }
}

// ---- fused comb + single_li per-level partial GEMM (fp32) --------------------
__global__ __launch_bounds__(128) void combsl(
    const float* __restrict__ tp, const float* __restrict__ bilc,
    const float* __restrict__ Wsl, float* __restrict__ part)
{
    const int l = blockIdx.z, m0 = blockIdx.y*16, n0 = blockIdx.x*64;
    __shared__ __align__(16) float s1[16][520];
    __shared__ __align__(16) float Ws[16][68];
    const int tid = threadIdx.x;
    const int row = tid>>3, ln = tid&7;
    const int b = m0 + row;

    float mx = -1e30f;
    for (int i=0;i<64;i++){
        int z = ln + i*8;
        float v1 = bilc[(long)(l*3+0)*512+z] + bilc[(long)(l*3+1)*512+z] + bilc[(long)(l*3+2)*512+z];
#pragma unroll
        for (int a=0;a<3;a++)
            v1 += tp[((long)((2*l+0)*3+a))*BH + (long)b*512 + z];
        s1[row][z] = v1;
        mx = fmaxf(mx, v1);
    }
#pragma unroll
    for (int o=4;o>0;o>>=1) mx = fmaxf(mx, __shfl_xor_sync(0xffffffffu, mx, o, 8));
    float sm = 0.f;
    for (int i=0;i<64;i++){
        int z = ln + i*8;
        float e = expf(s1[row][z] - mx);
        s1[row][z] = e; sm += e;
    }
#pragma unroll
    for (int o=4;o>0;o>>=1) sm += __shfl_xor_sync(0xffffffffu, sm, o, 8);
    float inv = 1.f/sm;
    for (int i=0;i<64;i++){
        int z = ln + i*8;
        float v2 = bilc[(long)(l*3+0)*512+z] + bilc[(long)(l*3+1)*512+z] + bilc[(long)(l*3+2)*512+z];
#pragma unroll
        for (int a=0;a<3;a++)
            v2 += tp[((long)((2*l+1)*3+a))*BH + (long)b*512 + z];
        s1[row][z] = s1[row][z] * inv * sigf(v2);
    }
    __syncthreads();

    const int tx = tid&15, ty = tid>>4;
    const int wlm = tid>>1, wlk = (tid&1)<<3;
    float acc[2][4];
#pragma unroll
    for (int i=0;i<2;i++)
#pragma unroll
        for (int j=0;j<4;j++) acc[i][j]=0.f;
    for (int k0=0;k0<512;k0+=16){
        const float* wp = Wsl + (long)(n0+wlm)*2560 + l*512 + k0+wlk;
        float4 u0=*(const float4*)wp, u1=*(const float4*)(wp+4);
        Ws[wlk][wlm]=u0.x; Ws[wlk+1][wlm]=u0.y; Ws[wlk+2][wlm]=u0.z; Ws[wlk+3][wlm]=u0.w;
        Ws[wlk+4][wlm]=u1.x; Ws[wlk+5][wlm]=u1.y; Ws[wlk+6][wlm]=u1.z; Ws[wlk+7][wlm]=u1.w;
        __syncthreads();
#pragma unroll
        for (int kk=0;kk<16;kk++){
            float a0 = s1[ty*2][k0+kk], a1 = s1[ty*2+1][k0+kk];
            float4 w = *(const float4*)&Ws[kk][tx*4];
            acc[0][0]+=a0*w.x; acc[0][1]+=a0*w.y; acc[0][2]+=a0*w.z; acc[0][3]+=a0*w.w;
            acc[1][0]+=a1*w.x; acc[1][1]+=a1*w.y; acc[1][2]+=a1*w.z; acc[1][3]+=a1*w.w;
        }
        __syncthreads();
    }
#pragma unroll
    for (int i=0;i<2;i++)
#pragma unroll
        for (int j=0;j<4;j++)
            part[(long)l*BH + (long)(m0+ty*2+i)*512 + n0+tx*4+j] = acc[i][j];
}

// ---- combine partials + bias -> h_g(bf16 split); per-step linear -> y --------
__global__ void y_kernel(const float* __restrict__ part, const float* __restrict__ bsl,
                         __nv_bfloat16* __restrict__ hgh, __nv_bfloat16* __restrict__ hgl,
                         const float* __restrict__ wlin_t,
                         const float* __restrict__ blin_t, float* __restrict__ outp)
{
    int b = blockIdx.x, tid = threadIdx.x;
    float s = 0.f;
    for (int j=tid; j<512; j+=128){
        long idx = (long)b*512 + j;
        float h = bsl[j] + part[idx] + part[BH+idx] + part[2L*BH+idx]
                + part[3L*BH+idx] + part[4L*BH+idx];
        __nv_bfloat16 hh = __float2bfloat16(h);
        hgh[idx] = hh;
        hgl[idx] = __float2bfloat16(h - __bfloat162float(hh));
        s += h * wlin_t[j];
    }
    __shared__ float red[128];
    red[tid]=s; __syncthreads();
    for (int st=64; st>0; st>>=1){ if (tid<st) red[tid]+=red[tid+st]; __syncthreads(); }
    if (tid==0) outp[b] = red[0] + blin_t[0];
}

extern "C" void kernel_launch(void* const* d_in, const int* in_sizes, int n_in,
                              void* d_out, int out_size)
{
    const float* x     = (const float*)d_in[0];
    const float* Wx    = (const float*)d_in[1];
    const float* Wh    = (const float*)d_in[2];
    const float* bl    = (const float*)d_in[3];
    const float* Wg_h  = (const float*)d_in[4];
    const float* Wg_p  = (const float*)d_in[5];
    const float* bg    = (const float*)d_in[6];
    const float* Wilc  = (const float*)d_in[7];
    const float* bilc  = (const float*)d_in[8];
    const float* Wsl   = (const float*)d_in[9];
    const float* bsl   = (const float*)d_in[10];
    const float* Wlin  = (const float*)d_in[11];
    const float* blin  = (const float*)d_in[12];
    float* out = (float*)d_out;

    float *c, *tp, *slp;
    __nv_bfloat16 *wxh, *wxl, *whh, *whl, *xh, *xl, *hbh, *hbl;
    __nv_bfloat16 *ghh, *ghl, *gph, *gpl, *hgh, *hgl;
    __nv_bfloat16 *wth, *wtl, *ichi, *iclo, *cchi, *cclo;
    cudaGetSymbolAddress((void**)&c,   g_c);
    cudaGetSymbolAddress((void**)&tp,  g_tp);
    cudaGetSymbolAddress((void**)&slp, g_slp);
    cudaGetSymbolAddress((void**)&wxh, g_Wxhi);
    cudaGetSymbolAddress((void**)&wxl, g_Wxlo);
    cudaGetSymbolAddress((void**)&whh, g_Whhi);
    cudaGetSymbolAddress((void**)&whl, g_Whlo);
    cudaGetSymbolAddress((void**)&ghh, g_Wghh);
    cudaGetSymbolAddress((void**)&ghl, g_Wghl);
    cudaGetSymbolAddress((void**)&gph, g_Wgph);
    cudaGetSymbolAddress((void**)&gpl, g_Wgpl);
    cudaGetSymbolAddress((void**)&wth, g_Wthi);
    cudaGetSymbolAddress((void**)&wtl, g_Wtlo);
    cudaGetSymbolAddress((void**)&xh,  g_xh);
    cudaGetSymbolAddress((void**)&xl,  g_xl);
    cudaGetSymbolAddress((void**)&hbh, g_hbh);
    cudaGetSymbolAddress((void**)&hbl, g_hbl);
    cudaGetSymbolAddress((void**)&hgh, g_hgh);
    cudaGetSymbolAddress((void**)&hgl, g_hgl);
    cudaGetSymbolAddress((void**)&ichi, g_ichi);
    cudaGetSymbolAddress((void**)&iclo, g_iclo);
    cudaGetSymbolAddress((void**)&cchi, g_cchi);
    cudaGetSymbolAddress((void**)&cclo, g_cclo);

    conv_w_lstm<<<1024,256>>>(Wx, Wh, wxh, wxl, whh, whl);
    conv_wg<<<1024,256>>>(Wg_h, Wg_p, ghh, ghl, gph, gpl);
    conv_wilc<<<dim3(16,16,15),256>>>(Wilc, wth, wtl);
    conv_x<<<512,256>>>(x, xh, xl);
    zero_kernel<<<256,256>>>(c, hbh, hbl, hgh, hgl);

    for (int t=0; t<TT; t++){
        int p = t & 1, q = p ^ 1;
        const float* cp = c + (long)p*NLA*BH;
        float*       cq = c + (long)q*NLA*BH;
        const __nv_bfloat16* hbhp = hbh + (long)p*NLA*BH;
        __nv_bfloat16*       hbhq = hbh + (long)q*NLA*BH;
        const __nv_bfloat16* hblp = hbl + (long)p*NLA*BH;
        __nv_bfloat16*       hblq = hbl + (long)q*NLA*BH;
        const __nv_bfloat16* hghp = hgh + (long)p*BH;
        __nv_bfloat16*       hghq = hgh + (long)q*BH;
        const __nv_bfloat16* hglp = hgl + (long)p*BH;
        __nv_bfloat16*       hglq = hgl + (long)q*BH;

        for (int l=0; l<5; l++){
            const __nv_bfloat16 *A1h_, *A1l_;
            long a1zs;
            if (l==0){ A1h_ = xh + (long)t*BH; A1l_ = xl + (long)t*BH; a1zs = 0; }
            else { A1h_ = hbhq + (long)(l-1)*3*BH; A1l_ = hblq + (long)(l-1)*3*BH; a1zs = BH; }
            lstm_mma<<<dim3(16,4,3),256>>>(
                A1h_, A1l_, a1zs,
                hbhp + (long)l*3*BH, hblp + (long)l*3*BH,
                wxh + (long)l*4*HH, wxl + (long)l*4*HH,
                whh + (long)l*4*HH, whl + (long)l*4*HH,
                bl, l, cp + (long)l*3*BH,
                cq + (long)l*3*BH,
                hbhq + (long)l*3*BH, hblq + (long)l*3*BH);
        }
        cell_mma<<<dim3(16,4,15),192>>>(
            hghp, hglp, hbhq, hblq,
            ghh, ghl, gph, gpl,
            bg, cq, ichi, iclo, cchi, cclo);
        t12_mma<<<dim3(16,4,15),128>>>(ichi, iclo, cchi, cclo, wth, wtl, tp);
        combsl<<<dim3(8,8,5),128>>>(tp, bilc, Wsl, slp);
        y_kernel<<<128,128>>>(slp, bsl, hghq, hglq, Wlin + (long)t*HD, blin + t, out + (long)t*BSZ);
    }
}

// round 10
// speedup vs baseline: 5.9081x; 1.2373x over previous
#include <cuda_runtime.h>
#include <cuda_bf16.h>
#include <math.h>
#include <stdint.h>

#define TT 64
#define BSZ 128
#define HD 512
#define NLA 15
#define BH (BSZ*HD)
#define HH (HD*HD)
#define NWL (3L*5*4*512*512)
#define NWG (5L*3*3*512*512)

__device__ float g_c[2][NLA][BH];
__device__ float g_tp[30][BH];
__device__ float g_slp[5][BH];

__device__ __nv_bfloat16 g_Wxhi[NWL], g_Wxlo[NWL], g_Whhi[NWL], g_Whlo[NWL];
__device__ __nv_bfloat16 g_Wghh[NWG], g_Wghl[NWG], g_Wgph[NWG], g_Wgpl[NWG];
__device__ __nv_bfloat16 g_Wthi[15L*HH], g_Wtlo[15L*HH];
__device__ __nv_bfloat16 g_xh[(long)TT*BH], g_xl[(long)TT*BH];
__device__ __nv_bfloat16 g_hbh[2][NLA][BH], g_hbl[2][NLA][BH];
__device__ __nv_bfloat16 g_hgh[2][BH], g_hgl[2][BH];
__device__ __nv_bfloat16 g_ichi[NLA][BH], g_iclo[NLA][BH];
__device__ __nv_bfloat16 g_cchi[NLA][BH], g_cclo[NLA][BH];

__device__ __forceinline__ float sigf(float x){ return 1.0f/(1.0f+expf(-x)); }

__global__ void zero_kernel(float* c0, __nv_bfloat16* hbh0, __nv_bfloat16* hbl0,
                            __nv_bfloat16* hgh0, __nv_bfloat16* hgl0){
    int n = NLA*BH;
    __nv_bfloat16 z = __float2bfloat16(0.f);
    for (int i = blockIdx.x*blockDim.x+threadIdx.x; i < n; i += gridDim.x*blockDim.x){
        c0[i]=0.f; hbh0[i]=z; hbl0[i]=z;
        if (i<BH){ hgh0[i]=z; hgl0[i]=z; }
    }
}

__global__ void conv_w_lstm(const float* __restrict__ Wx, const float* __restrict__ Wh,
    __nv_bfloat16* xh, __nv_bfloat16* xl, __nv_bfloat16* hh, __nv_bfloat16* hl){
    for (long i = (long)blockIdx.x*blockDim.x+threadIdx.x; i < NWL;
         i += (long)gridDim.x*blockDim.x){
        float w = Wx[i];
        __nv_bfloat16 hi = __float2bfloat16(w);
        xh[i] = hi; xl[i] = __float2bfloat16(w - __bfloat162float(hi));
        w = Wh[i];
        hi = __float2bfloat16(w);
        hh[i] = hi; hl[i] = __float2bfloat16(w - __bfloat162float(hi));
    }
}

__global__ void conv_wg(const float* __restrict__ Gh, const float* __restrict__ Gp,
    __nv_bfloat16* ghh, __nv_bfloat16* ghl, __nv_bfloat16* gph, __nv_bfloat16* gpl){
    for (long i = (long)blockIdx.x*blockDim.x+threadIdx.x; i < NWG;
         i += (long)gridDim.x*blockDim.x){
        float w = Gh[i];
        __nv_bfloat16 hi = __float2bfloat16(w);
        ghh[i] = hi; ghl[i] = __float2bfloat16(w - __bfloat162float(hi));
        w = Gp[i];
        hi = __float2bfloat16(w);
        gph[i] = hi; gpl[i] = __float2bfloat16(w - __bfloat162float(hi));
    }
}

__global__ void conv_wilc(const float* __restrict__ W,
                          __nv_bfloat16* th, __nv_bfloat16* tl){
    int zb = blockIdx.z;
    int z0 = blockIdx.y*32, y0 = blockIdx.x*32;
    __shared__ float s[32][33];
    int tx = threadIdx.x&31, ty = threadIdx.x>>5;
    const float* Wb = W + (long)zb*HH;
#pragma unroll
    for (int r=0;r<4;r++)
        s[ty+r*8][tx] = Wb[(long)(z0+ty+r*8)*512 + y0+tx];
    __syncthreads();
#pragma unroll
    for (int r=0;r<4;r++){
        float w = s[tx][ty+r*8];
        __nv_bfloat16 hi = __float2bfloat16(w);
        long o = (long)zb*HH + (long)(y0+ty+r*8)*512 + z0+tx;
        th[o]=hi; tl[o]=__float2bfloat16(w - __bfloat162float(hi));
    }
}

__global__ void conv_x(const float* __restrict__ x, __nv_bfloat16* xh, __nv_bfloat16* xl){
    const long N = (long)TT*BH;
    for (long i = (long)blockIdx.x*blockDim.x+threadIdx.x; i < N;
         i += (long)gridDim.x*blockDim.x){
        float w = x[i];
        __nv_bfloat16 hi = __float2bfloat16(w);
        xh[i] = hi; xl[i] = __float2bfloat16(w - __bfloat162float(hi));
    }
}

__device__ __forceinline__ void ldsm4(uint32_t addr, uint32_t &r0, uint32_t &r1,
                                      uint32_t &r2, uint32_t &r3){
    asm volatile("ldmatrix.sync.aligned.m8n8.x4.shared.b16 {%0,%1,%2,%3}, [%4];"
        : "=r"(r0),"=r"(r1),"=r"(r2),"=r"(r3) : "r"(addr));
}
__device__ __forceinline__ void mma16816(float* c, const uint32_t* a,
                                         uint32_t b0, uint32_t b1){
    asm volatile("mma.sync.aligned.m16n8k16.row.col.f32.bf16.bf16.f32 "
        "{%0,%1,%2,%3},{%4,%5,%6,%7},{%8,%9},{%0,%1,%2,%3};"
        : "+f"(c[0]),"+f"(c[1]),"+f"(c[2]),"+f"(c[3])
        : "r"(a[0]),"r"(a[1]),"r"(a[2]),"r"(a[3]),"r"(b0),"r"(b1));
}
__device__ __forceinline__ void cpa16(uint32_t dst, const void* src){
    asm volatile("cp.async.ca.shared.global [%0], [%1], 16;" :: "r"(dst), "l"(src));
}
__device__ __forceinline__ void cpa_commit(){ asm volatile("cp.async.commit_group;"); }

// ---- LSTM level: 3-stage pipelined split-bf16 mma, 384 blocks ----------------
// grid (32 n-tiles[16/gate], 4 m-tiles[32], 3 axes), 128 thr (warp = gate).
__global__ __launch_bounds__(128) void lstm_mma(
    const __nv_bfloat16* __restrict__ A1h, const __nv_bfloat16* __restrict__ A1l, long a1zs,
    const __nv_bfloat16* __restrict__ A2h, const __nv_bfloat16* __restrict__ A2l,
    const __nv_bfloat16* __restrict__ W1h, const __nv_bfloat16* __restrict__ W1l,
    const __nv_bfloat16* __restrict__ W2h, const __nv_bfloat16* __restrict__ W2l,
    const float* __restrict__ bl, int l, const float* __restrict__ cpb,
    float* __restrict__ cqb,
    __nv_bfloat16* __restrict__ hbhq, __nv_bfloat16* __restrict__ hblq)
{
    const int a = blockIdx.z;
    const int m0 = blockIdx.y*32, n0 = blockIdx.x*16;
    const int tid = threadIdx.x, lane = tid&31, g = tid>>5;

    __shared__ __align__(16) __nv_bfloat16 sA[3][2][32][40];
    __shared__ __align__(16) __nv_bfloat16 sW[3][2][4][16][40];

    float C[2][2][4];
#pragma unroll
    for (int mh=0;mh<2;mh++)
#pragma unroll
        for (int f=0;f<2;f++)
#pragma unroll
            for (int r=0;r<4;r++) C[mh][f][r]=0.f;

    const __nv_bfloat16* Ah_[2] = {A1h + (long)a*a1zs, A2h + (long)a*BH};
    const __nv_bfloat16* Al_[2] = {A1l + (long)a*a1zs, A2l + (long)a*BH};
    const __nv_bfloat16* Wp[2][2] = {
        {W1h + (long)a*20*HH, W1l + (long)a*20*HH},
        {W2h + (long)a*20*HH, W2l + (long)a*20*HH}};

    const uint32_t sA_base = (uint32_t)__cvta_generic_to_shared(&sA[0][0][0][0]);
    const uint32_t sW_base = (uint32_t)__cvta_generic_to_shared(&sW[0][0][0][0][0]);

    const int a_row = lane&15, a_ko = (lane>>4)*8;
    const int b_r = lane&7, b_sel = lane>>3;
    const int b_rowoff = b_r + ((b_sel>>1)?8:0), b_ko = (b_sel&1)*8;

    auto prefetch = [&](int kc2){
        int st = kc2 % 3, s = kc2>>4, k0 = (kc2&15)*32;
#pragma unroll
        for (int it=0; it<2; it++){   // A: 256 x 16B
            int idx = tid + it*128;
            int q = idx&3, row = (idx>>2)&31, hl = (idx>>7)&1;
            const __nv_bfloat16* src = (hl ? Al_[s] : Ah_[s]) + (long)(m0+row)*512 + k0 + q*8;
            cpa16(sA_base + (uint32_t)((((st*2+hl)*32 + row)*40 + q*8)*2), src);
        }
#pragma unroll
        for (int it=0; it<4; it++){   // W: 512 x 16B
            int idx = tid + it*128;
            int q = idx&3, n = (idx>>2)&15, gg = (idx>>6)&3, hl = (idx>>8)&1;
            const __nv_bfloat16* src = Wp[s][hl] + (long)gg*HH + (long)(n0+n)*512 + k0 + q*8;
            cpa16(sW_base + (uint32_t)(((((st*2+hl)*4+gg)*16 + n)*40 + q*8)*2), src);
        }
        cpa_commit();
    };

    prefetch(0); prefetch(1);
    for (int kc2=0; kc2<32; kc2++){
        const int st = kc2 % 3;
        if (kc2+2 < 32){
            prefetch(kc2+2);
            asm volatile("cp.async.wait_group 2;");
        } else if (kc2+1 < 32){
            asm volatile("cp.async.wait_group 1;");
        } else {
            asm volatile("cp.async.wait_group 0;");
        }
        __syncthreads();
#pragma unroll
        for (int kf=0;kf<2;kf++){
            uint32_t ah[2][4], al[2][4];
#pragma unroll
            for (int mh=0;mh<2;mh++){
                uint32_t ad = sA_base + (uint32_t)(((((st*2+0)*32) + mh*16 + a_row)*40 + kf*16 + a_ko)*2);
                ldsm4(ad, ah[mh][0], ah[mh][1], ah[mh][2], ah[mh][3]);
                ad = sA_base + (uint32_t)(((((st*2+1)*32) + mh*16 + a_row)*40 + kf*16 + a_ko)*2);
                ldsm4(ad, al[mh][0], al[mh][1], al[mh][2], al[mh][3]);
            }
            uint32_t bh0,bh1,bh2,bh3, bl0,bl1,bl2,bl3;
            {
                uint32_t bd = sW_base + (uint32_t)(((((st*2+0)*4+g)*16 + b_rowoff)*40 + kf*16 + b_ko)*2);
                ldsm4(bd, bh0,bh1,bh2,bh3);
                bd = sW_base + (uint32_t)(((((st*2+1)*4+g)*16 + b_rowoff)*40 + kf*16 + b_ko)*2);
                ldsm4(bd, bl0,bl1,bl2,bl3);
            }
#pragma unroll
            for (int mh=0;mh<2;mh++){
                mma16816(C[mh][0], ah[mh], bh0, bh1);
                mma16816(C[mh][1], ah[mh], bh2, bh3);
                mma16816(C[mh][0], ah[mh], bl0, bl1);
                mma16816(C[mh][1], ah[mh], bl2, bl3);
                mma16816(C[mh][0], al[mh], bh0, bh1);
                mma16816(C[mh][1], al[mh], bh2, bh3);
            }
        }
        __syncthreads();
    }

    // epilogue: preS[4][32][16] f32 (8 KB, reuse sW)
    float* preS = (float*)&sW[0][0][0][0][0];
    {
        int r = lane>>2, i2 = (lane&3)*2;
#pragma unroll
        for (int mh=0;mh<2;mh++)
#pragma unroll
            for (int f=0;f<2;f++){
                int col = f*8 + i2;
                preS[(g*32 + mh*16 + r)*16 + col]     = C[mh][f][0];
                preS[(g*32 + mh*16 + r)*16 + col+1]   = C[mh][f][1];
                preS[(g*32 + mh*16 + r+8)*16 + col]   = C[mh][f][2];
                preS[(g*32 + mh*16 + r+8)*16 + col+1] = C[mh][f][3];
            }
    }
    __syncthreads();
    {
        const float* cp = cpb + (long)a*BH;
        for (int cell = tid; cell < 512; cell += 128){
            int m = cell>>4, n = cell&15;
            int gn = n0 + n;
            float p[4];
#pragma unroll
            for (int gg=0;gg<4;gg++)
                p[gg] = preS[(gg*32+m)*16 + n] + bl[((long)(a*5+l)*4+gg)*512 + gn];
            long o = (long)a*BH + (long)(m0+m)*512 + gn;
            float cn = sigf(p[1])*cp[(long)(m0+m)*512+gn] + sigf(p[0])*tanhf(p[2]);
            float hv = sigf(p[3])*tanhf(cn);
            cqb[o] = cn;
            __nv_bfloat16 hh = __float2bfloat16(hv);
            hbhq[o] = hh;
            hblq[o] = __float2bfloat16(hv - __bfloat162float(hh));
        }
    }
}

// ---- cell block: split-bf16 3-gate mma + epilogue emitting bf16 ic/cc splits -
__global__ __launch_bounds__(192) void cell_mma(
    const __nv_bfloat16* __restrict__ Hgh, const __nv_bfloat16* __restrict__ Hgl,
    const __nv_bfloat16* __restrict__ Hbh, const __nv_bfloat16* __restrict__ Hbl,
    const __nv_bfloat16* __restrict__ Ghh, const __nv_bfloat16* __restrict__ Ghl,
    const __nv_bfloat16* __restrict__ Gph, const __nv_bfloat16* __restrict__ Gpl,
    const float* __restrict__ bg, const float* __restrict__ scb,
    __nv_bfloat16* __restrict__ ichi, __nv_bfloat16* __restrict__ iclo,
    __nv_bfloat16* __restrict__ cchi, __nv_bfloat16* __restrict__ cclo)
{
    const int zb = blockIdx.z;
    const int m0 = blockIdx.y*32, n0 = blockIdx.x*32;
    const int tid = threadIdx.x, lane = tid&31, wid = tid>>5;
    const int g = wid>>1, nb = (wid&1)*16;

    __shared__ __align__(16) __nv_bfloat16 sA[2][2][32][40];
    __shared__ __align__(16) __nv_bfloat16 sW[2][2][3][32][40];

    float C[2][2][4];
#pragma unroll
    for (int mh=0;mh<2;mh++)
#pragma unroll
        for (int f=0;f<2;f++)
#pragma unroll
            for (int r=0;r<4;r++) C[mh][f][r]=0.f;

    const __nv_bfloat16* Ah_[2] = {Hgh, Hbh + (long)zb*BH};
    const __nv_bfloat16* Al_[2] = {Hgl, Hbl + (long)zb*BH};
    const __nv_bfloat16* Wp[2][2] = {
        {Ghh + (long)zb*3*HH, Ghl + (long)zb*3*HH},
        {Gph + (long)zb*3*HH, Gpl + (long)zb*3*HH}};

    const uint32_t sA_base = (uint32_t)__cvta_generic_to_shared(&sA[0][0][0][0]);
    const uint32_t sW_base = (uint32_t)__cvta_generic_to_shared(&sW[0][0][0][0][0]);

    const int a_row = lane&15, a_ko = (lane>>4)*8;
    const int b_r = lane&7, b_sel = lane>>3;
    const int b_rowoff = b_r + ((b_sel>>1)?8:0), b_ko = (b_sel&1)*8;

    auto prefetch = [&](int kc2){
        int st = kc2&1, s = kc2>>4, k0 = (kc2&15)*32;
#pragma unroll
        for (int it=0; it<2; it++){
            int idx = tid + it*192;
            if (idx < 256){
                int hl = idx>>7, lm = (idx>>2)&31, lq = idx&3;
                const __nv_bfloat16* src = (hl ? Al_[s] : Ah_[s]) + (long)(m0+lm)*512 + k0 + lq*8;
                cpa16(sA_base + (uint32_t)((((st*2+hl)*32 + lm)*40 + lq*8)*2), src);
            }
        }
#pragma unroll
        for (int it=0; it<4; it++){
            int idx = tid + it*192;
            int q = idx&3, n = (idx>>2)&31, rest = idx>>7;
            int gg = rest % 3, hl = rest / 3;
            const __nv_bfloat16* src = Wp[s][hl] + (long)gg*HH + (long)(n0+n)*512 + k0 + q*8;
            cpa16(sW_base + (uint32_t)(((((st*2+hl)*3+gg)*32 + n)*40 + q*8)*2), src);
        }
        cpa_commit();
    };

    prefetch(0);
    for (int kc2=0; kc2<32; kc2++){
        const int st = kc2&1;
        if (kc2+1 < 32){
            prefetch(kc2+1);
            asm volatile("cp.async.wait_group 1;");
        } else {
            asm volatile("cp.async.wait_group 0;");
        }
        __syncthreads();
#pragma unroll
        for (int kf=0;kf<2;kf++){
            uint32_t ah[2][4], al[2][4];
#pragma unroll
            for (int mh=0;mh<2;mh++){
                uint32_t ad = sA_base + (uint32_t)(((((st*2+0)*32) + mh*16 + a_row)*40 + kf*16 + a_ko)*2);
                ldsm4(ad, ah[mh][0], ah[mh][1], ah[mh][2], ah[mh][3]);
                ad = sA_base + (uint32_t)(((((st*2+1)*32) + mh*16 + a_row)*40 + kf*16 + a_ko)*2);
                ldsm4(ad, al[mh][0], al[mh][1], al[mh][2], al[mh][3]);
            }
            uint32_t bh0,bh1,bh2,bh3, bl0,bl1,bl2,bl3;
            {
                uint32_t bd = sW_base + (uint32_t)((((((st*2+0)*3)+g)*32 + nb + b_rowoff)*40 + kf*16 + b_ko)*2);
                ldsm4(bd, bh0,bh1,bh2,bh3);
                bd = sW_base + (uint32_t)((((((st*2+1)*3)+g)*32 + nb + b_rowoff)*40 + kf*16 + b_ko)*2);
                ldsm4(bd, bl0,bl1,bl2,bl3);
            }
#pragma unroll
            for (int mh=0;mh<2;mh++){
                mma16816(C[mh][0], ah[mh], bh0, bh1);
                mma16816(C[mh][1], ah[mh], bh2, bh3);
                mma16816(C[mh][0], ah[mh], bl0, bl1);
                mma16816(C[mh][1], ah[mh], bl2, bl3);
                mma16816(C[mh][0], al[mh], bh0, bh1);
                mma16816(C[mh][1], al[mh], bh2, bh3);
            }
        }
        __syncthreads();
    }

    float* preS = (float*)&sW[0][0][0][0][0];
    {
        int r = lane>>2, i2 = (lane&3)*2;
#pragma unroll
        for (int mh=0;mh<2;mh++)
#pragma unroll
            for (int f=0;f<2;f++){
                int col = nb + f*8 + i2;
                preS[(g*32 + mh*16 + r)*32 + col]     = C[mh][f][0];
                preS[(g*32 + mh*16 + r)*32 + col+1]   = C[mh][f][1];
                preS[(g*32 + mh*16 + r+8)*32 + col]   = C[mh][f][2];
                preS[(g*32 + mh*16 + r+8)*32 + col+1] = C[mh][f][3];
            }
    }
    __syncthreads();
    {
        const float* sc = scb + (long)zb*BH;
        for (int cell = tid; cell < 1024; cell += 192){
            int m = cell>>5, n = cell&31;
            int gn = n0 + n;
            float p[3];
#pragma unroll
            for (int gg=0;gg<3;gg++)
                p[gg] = preS[(gg*32+m)*32 + n] + bg[((long)zb*3+gg)*512 + gn];
            long r = (long)(m0+m)*512 + gn;
            float icv = sigf(p[0]) * sc[r];
            float ccv = sigf(p[1])*tanhf(p[2]) + icv;
            long o = (long)zb*BH + r;
            __nv_bfloat16 ih = __float2bfloat16(icv);
            ichi[o] = ih; iclo[o] = __float2bfloat16(icv - __bfloat162float(ih));
            __nv_bfloat16 ch = __float2bfloat16(ccv);
            cchi[o] = ch; cclo[o] = __float2bfloat16(ccv - __bfloat162float(ch));
        }
    }
}

// ---- t12: dual-stream split-bf16 mma vs shared Wt tile -----------------------
__global__ __launch_bounds__(128) void t12_mma(
    const __nv_bfloat16* __restrict__ ichi, const __nv_bfloat16* __restrict__ iclo,
    const __nv_bfloat16* __restrict__ cchi, const __nv_bfloat16* __restrict__ cclo,
    const __nv_bfloat16* __restrict__ Wth, const __nv_bfloat16* __restrict__ Wtl,
    float* __restrict__ tp)
{
    const int zb = blockIdx.z;
    const int l = zb/3, a = zb%3;
    const int m0 = blockIdx.y*32, n0 = blockIdx.x*32;
    const int tid = threadIdx.x, lane = tid&31, wid = tid>>5;
    const int s = wid>>1, nb = (wid&1)*16;

    __shared__ __align__(16) __nv_bfloat16 sA[2][2][2][32][40];
    __shared__ __align__(16) __nv_bfloat16 sW[2][2][32][40];

    float C[2][2][4];
#pragma unroll
    for (int mh=0;mh<2;mh++)
#pragma unroll
        for (int f=0;f<2;f++)
#pragma unroll
            for (int r=0;r<4;r++) C[mh][f][r]=0.f;

    const __nv_bfloat16* Asrc[2][2] = {
        {ichi + (long)zb*BH, iclo + (long)zb*BH},
        {cchi + (long)zb*BH, cclo + (long)zb*BH}};
    const __nv_bfloat16* Wsrc[2] = {Wth + (long)zb*HH, Wtl + (long)zb*HH};

    const uint32_t sA_base = (uint32_t)__cvta_generic_to_shared(&sA[0][0][0][0][0]);
    const uint32_t sW_base = (uint32_t)__cvta_generic_to_shared(&sW[0][0][0][0]);

    const int a_row = lane&15, a_ko = (lane>>4)*8;
    const int b_r = lane&7, b_sel = lane>>3;
    const int b_rowoff = b_r + ((b_sel>>1)?8:0), b_ko = (b_sel&1)*8;

    auto prefetch = [&](int kc){
        int st = kc&1, k0 = kc*32;
#pragma unroll
        for (int it=0; it<4; it++){
            int idx = tid + it*128;
            int q = idx&3, row = (idx>>2)&31, hl = (idx>>7)&1, ss = (idx>>8)&1;
            const __nv_bfloat16* src = Asrc[ss][hl] + (long)(m0+row)*512 + k0 + q*8;
            cpa16(sA_base + (uint32_t)(((((st*2+ss)*2+hl)*32 + row)*40 + q*8)*2), src);
        }
#pragma unroll
        for (int it=0; it<2; it++){
            int idx = tid + it*128;
            int q = idx&3, row = (idx>>2)&31, hl = (idx>>7)&1;
            const __nv_bfloat16* src = Wsrc[hl] + (long)(n0+row)*512 + k0 + q*8;
            cpa16(sW_base + (uint32_t)((((st*2+hl)*32 + row)*40 + q*8)*2), src);
        }
        cpa_commit();
    };

    prefetch(0);
    for (int kc=0; kc<16; kc++){
        const int st = kc&1;
        if (kc+1 < 16){
            prefetch(kc+1);
            asm volatile("cp.async.wait_group 1;");
        } else {
            asm volatile("cp.async.wait_group 0;");
        }
        __syncthreads();
#pragma unroll
        for (int kf=0;kf<2;kf++){
            uint32_t ah[2][4], al[2][4];
#pragma unroll
            for (int mh=0;mh<2;mh++){
                uint32_t ad = sA_base + (uint32_t)((((((st*2+s)*2+0)*32) + mh*16 + a_row)*40 + kf*16 + a_ko)*2);
                ldsm4(ad, ah[mh][0], ah[mh][1], ah[mh][2], ah[mh][3]);
                ad = sA_base + (uint32_t)((((((st*2+s)*2+1)*32) + mh*16 + a_row)*40 + kf*16 + a_ko)*2);
                ldsm4(ad, al[mh][0], al[mh][1], al[mh][2], al[mh][3]);
            }
            uint32_t bh0,bh1,bh2,bh3, bl0,bl1,bl2,bl3;
            {
                uint32_t bd = sW_base + (uint32_t)((((st*2+0)*32 + nb + b_rowoff)*40 + kf*16 + b_ko)*2);
                ldsm4(bd, bh0,bh1,bh2,bh3);
                bd = sW_base + (uint32_t)((((st*2+1)*32 + nb + b_rowoff)*40 + kf*16 + b_ko)*2);
                ldsm4(bd, bl0,bl1,bl2,bl3);
            }
#pragma unroll
            for (int mh=0;mh<2;mh++){
                mma16816(C[mh][0], ah[mh], bh0, bh1);
                mma16816(C[mh][1], ah[mh], bh2, bh3);
                mma16816(C[mh][0], ah[mh], bl0, bl1);
                mma16816(C[mh][1], ah[mh], bl2, bl3);
                mma16816(C[mh][0], al[mh], bh0, bh1);
                mma16816(C[mh][1], al[mh], bh2, bh3);
            }
        }
        __syncthreads();
    }

    float* tpo = tp + ((long)((2*l+s)*3+a))*BH;
    {
        int r = lane>>2, i2 = (lane&3)*2;
#pragma unroll
        for (int mh=0;mh<2;mh++)
#pragma unroll
            for (int f=0;f<2;f++){
                int row = m0 + mh*16 + r;
                int col = n0 + nb + f*8 + i2;
                tpo[(long)row*512 + col]       = C[mh][f][0];
                tpo[(long)row*512 + col+1]     = C[mh][f][1];
                tpo[(long)(row+8)*512 + col]   = C[mh][f][2];
                tpo[(long)(row+8)*512 + col+1] = C[mh][f][3];
            }
    }
}

// ---- fused comb + single_li per-level partial GEMM (fp32) --------------------
__global__ __launch_bounds__(128) void combsl(
    const float* __restrict__ tp, const float* __restrict__ bilc,
    const float* __restrict__ Wsl, float* __restrict__ part)
{
    const int l = blockIdx.z, m0 = blockIdx.y*16, n0 = blockIdx.x*64;
    __shared__ __align__(16) float s1[16][520];
    __shared__ __align__(16) float Ws[16][68];
    const int tid = threadIdx.x;
    const int row = tid>>3, ln = tid&7;
    const int b = m0 + row;

    float mx = -1e30f;
    for (int i=0;i<64;i++){
        int z = ln + i*8;
        float v1 = bilc[(long)(l*3+0)*512+z] + bilc[(long)(l*3+1)*512+z] + bilc[(long)(l*3+2)*512+z];
#pragma unroll
        for (int a=0;a<3;a++)
            v1 += tp[((long)((2*l+0)*3+a))*BH + (long)b*512 + z];
        s1[row][z] = v1;
        mx = fmaxf(mx, v1);
    }
#pragma unroll
    for (int o=4;o>0;o>>=1) mx = fmaxf(mx, __shfl_xor_sync(0xffffffffu, mx, o, 8));
    float sm = 0.f;
    for (int i=0;i<64;i++){
        int z = ln + i*8;
        float e = expf(s1[row][z] - mx);
        s1[row][z] = e; sm += e;
    }
#pragma unroll
    for (int o=4;o>0;o>>=1) sm += __shfl_xor_sync(0xffffffffu, sm, o, 8);
    float inv = 1.f/sm;
    for (int i=0;i<64;i++){
        int z = ln + i*8;
        float v2 = bilc[(long)(l*3+0)*512+z] + bilc[(long)(l*3+1)*512+z] + bilc[(long)(l*3+2)*512+z];
#pragma unroll
        for (int a=0;a<3;a++)
            v2 += tp[((long)((2*l+1)*3+a))*BH + (long)b*512 + z];
        s1[row][z] = s1[row][z] * inv * sigf(v2);
    }
    __syncthreads();

    const int tx = tid&15, ty = tid>>4;
    const int wlm = tid>>1, wlk = (tid&1)<<3;
    float acc[2][4];
#pragma unroll
    for (int i=0;i<2;i++)
#pragma unroll
        for (int j=0;j<4;j++) acc[i][j]=0.f;
    for (int k0=0;k0<512;k0+=16){
        const float* wp = Wsl + (long)(n0+wlm)*2560 + l*512 + k0+wlk;
        float4 u0=*(const float4*)wp, u1=*(const float4*)(wp+4);
        Ws[wlk][wlm]=u0.x; Ws[wlk+1][wlm]=u0.y; Ws[wlk+2][wlm]=u0.z; Ws[wlk+3][wlm]=u0.w;
        Ws[wlk+4][wlm]=u1.x; Ws[wlk+5][wlm]=u1.y; Ws[wlk+6][wlm]=u1.z; Ws[wlk+7][wlm]=u1.w;
        __syncthreads();
#pragma unroll
        for (int kk=0;kk<16;kk++){
            float a0 = s1[ty*2][k0+kk], a1 = s1[ty*2+1][k0+kk];
            float4 w = *(const float4*)&Ws[kk][tx*4];
            acc[0][0]+=a0*w.x; acc[0][1]+=a0*w.y; acc[0][2]+=a0*w.z; acc[0][3]+=a0*w.w;
            acc[1][0]+=a1*w.x; acc[1][1]+=a1*w.y; acc[1][2]+=a1*w.z; acc[1][3]+=a1*w.w;
        }
        __syncthreads();
    }
#pragma unroll
    for (int i=0;i<2;i++)
#pragma unroll
        for (int j=0;j<4;j++)
            part[(long)l*BH + (long)(m0+ty*2+i)*512 + n0+tx*4+j] = acc[i][j];
}

// ---- combine partials + bias -> h_g(bf16 split); per-step linear -> y --------
__global__ void y_kernel(const float* __restrict__ part, const float* __restrict__ bsl,
                         __nv_bfloat16* __restrict__ hgh, __nv_bfloat16* __restrict__ hgl,
                         const float* __restrict__ wlin_t,
                         const float* __restrict__ blin_t, float* __restrict__ outp)
{
    int b = blockIdx.x, tid = threadIdx.x;
    float s = 0.f;
    for (int j=tid; j<512; j+=128){
        long idx = (long)b*512 + j;
        float h = bsl[j] + part[idx] + part[BH+idx] + part[2L*BH+idx]
                + part[3L*BH+idx] + part[4L*BH+idx];
        __nv_bfloat16 hh = __float2bfloat16(h);
        hgh[idx] = hh;
        hgl[idx] = __float2bfloat16(h - __bfloat162float(hh));
        s += h * wlin_t[j];
    }
    __shared__ float red[128];
    red[tid]=s; __syncthreads();
    for (int st=64; st>0; st>>=1){ if (tid<st) red[tid]+=red[tid+st]; __syncthreads(); }
    if (tid==0) outp[b] = red[0] + blin_t[0];
}

extern "C" void kernel_launch(void* const* d_in, const int* in_sizes, int n_in,
                              void* d_out, int out_size)
{
    const float* x     = (const float*)d_in[0];
    const float* Wx    = (const float*)d_in[1];
    const float* Wh    = (const float*)d_in[2];
    const float* bl    = (const float*)d_in[3];
    const float* Wg_h  = (const float*)d_in[4];
    const float* Wg_p  = (const float*)d_in[5];
    const float* bg    = (const float*)d_in[6];
    const float* Wilc  = (const float*)d_in[7];
    const float* bilc  = (const float*)d_in[8];
    const float* Wsl   = (const float*)d_in[9];
    const float* bsl   = (const float*)d_in[10];
    const float* Wlin  = (const float*)d_in[11];
    const float* blin  = (const float*)d_in[12];
    float* out = (float*)d_out;

    float *c, *tp, *slp;
    __nv_bfloat16 *wxh, *wxl, *whh, *whl, *xh, *xl, *hbh, *hbl;
    __nv_bfloat16 *ghh, *ghl, *gph, *gpl, *hgh, *hgl;
    __nv_bfloat16 *wth, *wtl, *ichi, *iclo, *cchi, *cclo;
    cudaGetSymbolAddress((void**)&c,   g_c);
    cudaGetSymbolAddress((void**)&tp,  g_tp);
    cudaGetSymbolAddress((void**)&slp, g_slp);
    cudaGetSymbolAddress((void**)&wxh, g_Wxhi);
    cudaGetSymbolAddress((void**)&wxl, g_Wxlo);
    cudaGetSymbolAddress((void**)&whh, g_Whhi);
    cudaGetSymbolAddress((void**)&whl, g_Whlo);
    cudaGetSymbolAddress((void**)&ghh, g_Wghh);
    cudaGetSymbolAddress((void**)&ghl, g_Wghl);
    cudaGetSymbolAddress((void**)&gph, g_Wgph);
    cudaGetSymbolAddress((void**)&gpl, g_Wgpl);
    cudaGetSymbolAddress((void**)&wth, g_Wthi);
    cudaGetSymbolAddress((void**)&wtl, g_Wtlo);
    cudaGetSymbolAddress((void**)&xh,  g_xh);
    cudaGetSymbolAddress((void**)&xl,  g_xl);
    cudaGetSymbolAddress((void**)&hbh, g_hbh);
    cudaGetSymbolAddress((void**)&hbl, g_hbl);
    cudaGetSymbolAddress((void**)&hgh, g_hgh);
    cudaGetSymbolAddress((void**)&hgl, g_hgl);
    cudaGetSymbolAddress((void**)&ichi, g_ichi);
    cudaGetSymbolAddress((void**)&iclo, g_iclo);
    cudaGetSymbolAddress((void**)&cchi, g_cchi);
    cudaGetSymbolAddress((void**)&cclo, g_cclo);

    conv_w_lstm<<<1024,256>>>(Wx, Wh, wxh, wxl, whh, whl);
    conv_wg<<<1024,256>>>(Wg_h, Wg_p, ghh, ghl, gph, gpl);
    conv_wilc<<<dim3(16,16,15),256>>>(Wilc, wth, wtl);
    conv_x<<<512,256>>>(x, xh, xl);
    zero_kernel<<<256,256>>>(c, hbh, hbl, hgh, hgl);

    for (int t=0; t<TT; t++){
        int p = t & 1, q = p ^ 1;
        const float* cp = c + (long)p*NLA*BH;
        float*       cq = c + (long)q*NLA*BH;
        const __nv_bfloat16* hbhp = hbh + (long)p*NLA*BH;
        __nv_bfloat16*       hbhq = hbh + (long)q*NLA*BH;
        const __nv_bfloat16* hblp = hbl + (long)p*NLA*BH;
        __nv_bfloat16*       hblq = hbl + (long)q*NLA*BH;
        const __nv_bfloat16* hghp = hgh + (long)p*BH;
        __nv_bfloat16*       hghq = hgh + (long)q*BH;
        const __nv_bfloat16* hglp = hgl + (long)p*BH;
        __nv_bfloat16*       hglq = hgl + (long)q*BH;

        for (int l=0; l<5; l++){
            const __nv_bfloat16 *A1h_, *A1l_;
            long a1zs;
            if (l==0){ A1h_ = xh + (long)t*BH; A1l_ = xl + (long)t*BH; a1zs = 0; }
            else { A1h_ = hbhq + (long)(l-1)*3*BH; A1l_ = hblq + (long)(l-1)*3*BH; a1zs = BH; }
            lstm_mma<<<dim3(32,4,3),128>>>(
                A1h_, A1l_, a1zs,
                hbhp + (long)l*3*BH, hblp + (long)l*3*BH,
                wxh + (long)l*4*HH, wxl + (long)l*4*HH,
                whh + (long)l*4*HH, whl + (long)l*4*HH,
                bl, l, cp + (long)l*3*BH,
                cq + (long)l*3*BH,
                hbhq + (long)l*3*BH, hblq + (long)l*3*BH);
        }
        cell_mma<<<dim3(16,4,15),192>>>(
            hghp, hglp, hbhq, hblq,
            ghh, ghl, gph, gpl,
            bg, cq, ichi, iclo, cchi, cclo);
        t12_mma<<<dim3(16,4,15),128>>>(ichi, iclo, cchi, cclo, wth, wtl, tp);
        combsl<<<dim3(8,8,5),128>>>(tp, bilc, Wsl, slp);
        y_kernel<<<128,128>>>(slp, bsl, hghq, hglq, Wlin + (long)t*HD, blin + t, out + (long)t*BSZ);
    }
}